// round 13
// baseline (speedup 1.0000x reference)
#include <cuda_runtime.h>

#define S      6561
#define Dm     34
#define HD     17
#define PH     20
#define PAC    18
#define FFd    2048
#define NH     2
#define HW     81
#define EPSV   1e-5f
#define ESTR   (NH * HW * HW)
// layer-0 FFN tiling: 16 f-segments of 128, 2 rows/thread, 64-thread blocks
#define NFSEG  16
#define FSEG   128
#define FCHK0  64
// layer-1 agent attention: 2 heads x 74 segs = 148 blocks
#define NSEG2  74
#define KSEG2  89
// agent FFN split
#define NFSEG2 32
#define FSEG2  64

typedef unsigned long long u64;

// ---- packed fp32 helpers ----
__device__ __forceinline__ u64 fma2(u64 a, u64 b, u64 c) {
    u64 d; asm("fma.rn.f32x2 %0, %1, %2, %3;" : "=l"(d) : "l"(a), "l"(b), "l"(c)); return d;
}
__device__ __forceinline__ u64 mul2(u64 a, u64 b) {
    u64 d; asm("mul.rn.f32x2 %0, %1, %2;" : "=l"(d) : "l"(a), "l"(b)); return d;
}
__device__ __forceinline__ u64 add2(u64 a, u64 b) {
    u64 d; asm("add.rn.f32x2 %0, %1, %2;" : "=l"(d) : "l"(a), "l"(b)); return d;
}
__device__ __forceinline__ float2 unpk(u64 v) {
    float2 f; asm("mov.b64 {%0, %1}, %2;" : "=f"(f.x), "=f"(f.y) : "l"(v)); return f;
}
__device__ __forceinline__ u64 pk(float x, float y) {
    u64 v; asm("mov.b64 %0, {%1, %2};" : "=l"(v) : "f"(x), "f"(y)); return v;
}

// ---- device-global scratch ----
__device__ unsigned g_cnt;
__device__ unsigned g_sense;
__device__ int   g_agent;
__device__ __align__(16) float g_emb[HW * 16];
__device__ __align__(16) float g_x[S * Dm];
__device__ __align__(16) float g_q[NH * S * PH];
__device__ __align__(16) float g_k[NH * S * PH];
__device__ __align__(16) float g_v[NH * S * PH];
__device__ __align__(16) float g_o[S * Dm];
__device__ __align__(16) float g_yp[NFSEG * S * Dm];
__device__ __align__(16) float g_QA[NH * HW * HD];
__device__ __align__(16) float g_QB[NH * HW * HD];
__device__ __align__(16) float g_KA[NH * HW * HD];
__device__ __align__(16) float g_KB[NH * HW * HD];
__device__ __align__(16) float g_VA[NH * HW * HD];
__device__ __align__(16) float g_VB[NH * HW * HD];
__device__ __align__(16) float g_E[4 * ESTR];    // EA, EB row-major; EC, ED TRANSPOSED
__device__ __align__(16) float g_pacca[NH * NSEG2 * HW * PAC];
__device__ float g_psuma[NH * NSEG2 * HW];
__device__ __align__(16) float g_xa[HW * Dm];
__device__ __align__(16) float g_ypa[NFSEG2 * HW * Dm];
__device__ __align__(16) float g_oa[HW * Dm];

// ---- sense-reversing grid barrier (all blocks resident) ----
__device__ __forceinline__ void gsync(unsigned& ls) {
    __syncthreads();
    if (threadIdx.x == 0) {
        unsigned ns = ls ^ 1u;
        __threadfence();
        unsigned old = atomicAdd(&g_cnt, 1u);
        if (old == gridDim.x - 1u) {
            g_cnt = 0u;
            __threadfence();
            atomicExch(&g_sense, ns);
        } else {
            while (atomicAdd(&g_sense, 0u) != ns) { __nanosleep(64); }
        }
        ls = ns;
        __threadfence();
    }
    __syncthreads();
}

// ---------------------------------------------------------------------------
// K1 (fused layer-0 front): conv+argmax -> basis QKV -> exp(logits)
//   -> structured attention -> tokens+out_proj+LN1. grid 148x512, 4 gsyncs.
// ---------------------------------------------------------------------------
__global__ void __launch_bounds__(512) layer0_pre(
    const float* __restrict__ obs,
    const float* __restrict__ c1w, const float* __restrict__ c1b,
    const float* __restrict__ c2w, const float* __restrict__ c2b,
    const float* __restrict__ ipw, const float* __restrict__ ipb,
    const float* __restrict__ opw, const float* __restrict__ opb,
    const float* __restrict__ gg,  const float* __restrict__ bb)
{
    __shared__ __align__(16) float sm[9344];
    int tid = threadIdx.x;
    int b = blockIdx.x;
    unsigned ls = 0;

    // ---- P0: conv1/conv2 + argmax (block 0) ----
    if (b == 0) {
        float* so  = sm;          // 162
        float* c1s = sm + 192;    // 1296
        for (int i = tid; i < 162; i += 512) so[i] = obs[i];
        __syncthreads();
        if (tid == 0) {
            float mx = so[0]; int mi = 0;
            for (int i = 1; i < 81; i++) if (so[i] > mx) { mx = so[i]; mi = i; }
            g_agent = mi;
        }
        for (int idx = tid; idx < 16 * 81; idx += 512) {
            int ch = idx / 81, pos = idx % 81, r = pos / 9, c = pos % 9;
            float acc = c1b[ch];
            for (int ci = 0; ci < 2; ci++)
                for (int dr = 0; dr < 3; dr++) {
                    int rr = r + dr - 1; if (rr < 0 || rr >= 9) continue;
                    for (int dc = 0; dc < 3; dc++) {
                        int cc = c + dc - 1; if (cc < 0 || cc >= 9) continue;
                        acc += so[ci * 81 + rr * 9 + cc] * c1w[((ch * 2 + ci) * 3 + dr) * 3 + dc];
                    }
                }
            c1s[idx] = fmaxf(acc, 0.f);
        }
        __syncthreads();
        for (int idx = tid; idx < 16 * 81; idx += 512) {
            int ch = idx / 81, pos = idx % 81, r = pos / 9, c = pos % 9;
            float acc = c2b[ch];
            for (int ci = 0; ci < 16; ci++)
                for (int dr = 0; dr < 3; dr++) {
                    int rr = r + dr - 1; if (rr < 0 || rr >= 9) continue;
                    for (int dc = 0; dc < 3; dc++) {
                        int cc = c + dc - 1; if (cc < 0 || cc >= 9) continue;
                        acc += c1s[ci * 81 + rr * 9 + cc] * c2w[((ch * 16 + ci) * 3 + dr) * 3 + dc];
                    }
                }
            g_emb[pos * 16 + ch] = fmaxf(acc, 0.f);
        }
    }
    gsync(ls);  // 1

    // ---- P1: basis QKV ----
    for (int idx = b * 512 + tid; idx < 162 * 102; idx += 148 * 512) {
        int v = idx / 102, c = idx % 102;
        const float* wr = ipw + c * Dm;
        float acc;
        if (v < 81) {
            int i = v;
            acc = ipb[c];
#pragma unroll
            for (int d = 0; d < 16; d++) acc = fmaf(g_emb[i * 16 + d], wr[d], acc);
            acc = fmaf((float)(i / 9) * 0.25f, wr[32], acc);
            acc = fmaf((float)(i % 9) * 0.25f, wr[33], acc);
        } else {
            int j = v - 81;
            acc = 0.f;
#pragma unroll
            for (int d = 0; d < 16; d++) acc = fmaf(g_emb[j * 16 + d], wr[16 + d], acc);
            acc = fmaf(-(float)(j / 9) * 0.25f, wr[32], acc);
            acc = fmaf(-(float)(j % 9) * 0.25f, wr[33], acc);
        }
        int kind = c / Dm;
        int cc = c % Dm;
        int h = cc / HD, dd = cc % HD;
        int off = (h * HW + (v % 81)) * HD + dd;
        if (kind == 0) {
            float sv = acc * rsqrtf(17.f);
            if (v < 81) g_QA[off] = sv; else g_QB[off] = sv;
        } else if (kind == 1) {
            if (v < 81) g_KA[off] = acc; else g_KB[off] = acc;
        } else {
            if (v < 81) g_VA[off] = acc; else g_VB[off] = acc;
        }
    }
    gsync(ls);  // 2

    // ---- P2: exp(logits); EC/ED stored transposed ----
    for (int idx = b * 512 + tid; idx < 4 * ESTR; idx += 148 * 512) {
        int p = idx / ESTR;
        int r = idx % ESTR;
        int h = r / (HW * HW);
        int q2 = r % (HW * HW);
        int i = q2 / HW, m = q2 % HW;
        const float* L;
        const float* R;
        if (p == 0)      { L = g_QA + (h * HW + i) * HD; R = g_KA + (h * HW + m) * HD; }
        else if (p == 1) { L = g_QA + (h * HW + i) * HD; R = g_KB + (h * HW + m) * HD; }
        else if (p == 2) { L = g_KA + (h * HW + i) * HD; R = g_QB + (h * HW + m) * HD; }
        else             { L = g_KB + (h * HW + i) * HD; R = g_QB + (h * HW + m) * HD; }
        float dot = 0.f;
#pragma unroll
        for (int d = 0; d < HD; d++) dot = fmaf(L[d], R[d], dot);
        g_E[idx] = __expf(dot);
    }
    gsync(ls);  // 3

    // ---- P3: structured attention -> g_o (162 units grid-stride) ----
    {
        float* sea  = sm;                 // 81
        float* seb  = sm + 96;            // 81
        float* sva  = sm + 192;           // 1458
        float* svb  = sm + 1664;          // 1458
        float* psum = sm + 3136;          // 324
        u64*   pacc = (u64*)(sm + 3464);  // 2916 u64
        for (int u = b; u < HW * NH; u += 148) {
            int i = u % HW, h = u / HW;
            __syncthreads();
            for (int t = tid; t < HW; t += 512) {
                sea[t] = g_E[0 * ESTR + (h * HW + i) * HW + t];
                seb[t] = g_E[1 * ESTR + (h * HW + i) * HW + t];
            }
            for (int t = tid; t < HW * 18; t += 512) {
                int m = t / 18, d = t % 18;
                sva[t] = (d < HD) ? g_VA[(h * HW + m) * HD + d] : 0.f;
                svb[t] = (d < HD) ? g_VB[(h * HW + m) * HD + d] : 0.f;
            }
            __syncthreads();
            int quad = tid >> 7;
            int j = tid & 127;
            if (j < HW) {
                bool isA = quad < 2;
                int lo = (quad & 1) ? 41 : 0;
                int hi = (quad & 1) ? HW : 41;
                const float* et = g_E + (isA ? 2 : 3) * ESTR + h * HW * HW + j;
                const float* se = isA ? sea : seb;
                const float* sv = isA ? sva : svb;
                float z = 0.f;
                u64 w[9];
#pragma unroll
                for (int k = 0; k < 9; k++) w[k] = 0ULL;
#pragma unroll 4
                for (int m = lo; m < hi; m++) {
                    float f = se[m] * et[m * HW];
                    z += f;
                    u64 fp = pk(f, f);
                    const u64* vr = (const u64*)(sv + m * 18);
#pragma unroll
                    for (int k = 0; k < 9; k++) w[k] = fma2(fp, vr[k], w[k]);
                }
                psum[quad * HW + j] = z;
                u64* pw = pacc + (quad * HW + j) * 9;
#pragma unroll
                for (int k = 0; k < 9; k++) pw[k] = w[k];
            }
            __syncthreads();
            if (tid < HW) {
                int jj = tid;
                float zm = psum[jj] + psum[HW + jj];
                float zn = psum[2 * HW + jj] + psum[3 * HW + jj];
                const u64* p0 = pacc + jj * 9;
                const u64* p1 = pacc + (HW + jj) * 9;
                const u64* p2 = pacc + (2 * HW + jj) * 9;
                const u64* p3 = pacc + (3 * HW + jj) * 9;
                float inv = 1.0f / (zm * zn);
                float* od = g_o + (i * HW + jj) * Dm + h * HD;
#pragma unroll
                for (int k = 0; k < 9; k++) {
                    float2 A = unpk(add2(p0[k], p1[k]));
                    float2 B = unpk(add2(p2[k], p3[k]));
                    int d = 2 * k;
                    od[d] = (A.x * zn + B.x * zm) * inv;
                    if (d + 1 < HD) od[d + 1] = (A.y * zn + B.y * zm) * inv;
                }
            }
        }
    }
    gsync(ls);  // 4

    // ---- P4: tokens + out_proj + residual + LN1 -> g_x ----
    // 128 tokens/block-unit, 4 d-quads of 9 (last 7). Units 52, blocks 0..51.
    {
        float* embs = sm;            // 1296
        float* ws   = sm + 1296;     // 1156
        float* bs   = sm + 2452;     // 34
        float* gs   = sm + 2486;     // 34
        float* bts  = sm + 2520;     // 34
        float* ys   = sm + 2560;     // 128*36 = 4608
        for (int u = b; u < (S + 127) / 128; u += 148) {
            __syncthreads();
            for (int i = tid; i < 1296; i += 512) embs[i] = g_emb[i];
            for (int i = tid; i < Dm * Dm; i += 512) ws[i] = opw[i];
            if (tid < Dm) { bs[tid] = opb[tid]; gs[tid] = gg[tid]; bts[tid] = bb[tid]; }
            __syncthreads();
            int q = tid >> 7;
            int lt = tid & 127;
            int t = u * 128 + lt;
            if (t < S) {
                int i = t / HW, j = t % HW;
                float orow[Dm];
#pragma unroll
                for (int d = 0; d < Dm; d++) orow[d] = g_o[t * Dm + d];
                int dlo = q * 9;
                int dhi = min(Dm, dlo + 9);
#pragma unroll 1
                for (int d = dlo; d < dhi; d++) {
                    float xv;
                    if (d < 16)       xv = embs[i * 16 + d];
                    else if (d < 32)  xv = embs[j * 16 + (d - 16)];
                    else if (d == 32) xv = ((float)(i / 9) - (float)(j / 9)) * 0.25f;
                    else              xv = ((float)(i % 9) - (float)(j % 9)) * 0.25f;
                    float a = bs[d] + xv;
                    const float* wp = ws + d * Dm;
#pragma unroll
                    for (int k = 0; k < Dm; k++) a = fmaf(orow[k], wp[k], a);
                    ys[lt * 36 + d] = a;
                }
            }
            __syncthreads();
            if (q == 0 && t < S) {
                float y[Dm];
#pragma unroll
                for (int d = 0; d < Dm; d++) y[d] = ys[lt * 36 + d];
                float m = 0.f;
#pragma unroll
                for (int d = 0; d < Dm; d++) m += y[d];
                m *= (1.0f / Dm);
                float v = 0.f;
#pragma unroll
                for (int d = 0; d < Dm; d++) { float tt = y[d] - m; v = fmaf(tt, tt, v); }
                v *= (1.0f / Dm);
                float inv = rsqrtf(v + EPSV);
#pragma unroll
                for (int d = 0; d < Dm; d++) g_x[t * Dm + d] = (y[d] - m) * inv * gs[d] + bts[d];
            }
        }
    }
}

// ---------------------------------------------------------------------------
// K2: layer-0 FFN partials — 2 rows/thread, 64-thread blocks, 6 blocks/SM
// (888 slots >= 832 blocks -> single wave). grid (52, 1, 16).
// ---------------------------------------------------------------------------
__global__ void __launch_bounds__(64, 6) ffn0(const float* __restrict__ l1w,
                                              const float* __restrict__ l1b,
                                              const float* __restrict__ l2w) {
    __shared__ __align__(16) float W1s[FCHK0 * 36];
    __shared__ __align__(16) float W2s[FCHK0 * 36];
    __shared__ float b1s[FCHK0];
    int tid = threadIdx.x;
    int row0 = blockIdx.x * 128 + tid;
    int row1 = row0 + 64;
    int fbase = blockIdx.z * FSEG;
    bool a0 = row0 < S, a1 = row1 < S;
    u64 x0[17], x1[17], y0[17], y1[17];
#pragma unroll
    for (int i = 0; i < 17; i++) { x0[i] = 0ULL; x1[i] = 0ULL; y0[i] = 0ULL; y1[i] = 0ULL; }
    if (a0) {
        const u64* p = (const u64*)(g_x + row0 * Dm);
#pragma unroll
        for (int i = 0; i < 17; i++) x0[i] = p[i];
    }
    if (a1) {
        const u64* p = (const u64*)(g_x + row1 * Dm);
#pragma unroll
        for (int i = 0; i < 17; i++) x1[i] = p[i];
    }
    for (int fc = fbase; fc < fbase + FSEG; fc += FCHK0) {
        for (int e = tid; e < FCHK0 * Dm; e += 64) {
            int f = e / Dm, d = e % Dm;
            W1s[f * 36 + d] = l1w[(fc + f) * Dm + d];
            W2s[f * 36 + d] = l2w[d * FFd + fc + f];
        }
        if (tid < FCHK0) b1s[tid] = l1b[fc + tid];
        __syncthreads();
#pragma unroll 2
        for (int f = 0; f < FCHK0; f++) {
            const ulonglong2* w2p = (const ulonglong2*)(W1s + f * 36);
            const u64*        w1p = (const u64*)(W1s + f * 36);
            ulonglong2 a0v = w2p[0], a1v = w2p[1], a2v = w2p[2], a3v = w2p[3];
            ulonglong2 a4v = w2p[4], a5v = w2p[5], a6v = w2p[6], a7v = w2p[7];
            u64 a16 = w1p[16];
            u64 t0 = mul2(x0[0], a0v.x),  t1 = mul2(x0[1], a0v.y);
            u64 u0 = mul2(x1[0], a0v.x),  u1 = mul2(x1[1], a0v.y);
            t0 = fma2(x0[2], a1v.x, t0);  t1 = fma2(x0[3], a1v.y, t1);
            u0 = fma2(x1[2], a1v.x, u0);  u1 = fma2(x1[3], a1v.y, u1);
            t0 = fma2(x0[4], a2v.x, t0);  t1 = fma2(x0[5], a2v.y, t1);
            u0 = fma2(x1[4], a2v.x, u0);  u1 = fma2(x1[5], a2v.y, u1);
            t0 = fma2(x0[6], a3v.x, t0);  t1 = fma2(x0[7], a3v.y, t1);
            u0 = fma2(x1[6], a3v.x, u0);  u1 = fma2(x1[7], a3v.y, u1);
            t0 = fma2(x0[8], a4v.x, t0);  t1 = fma2(x0[9], a4v.y, t1);
            u0 = fma2(x1[8], a4v.x, u0);  u1 = fma2(x1[9], a4v.y, u1);
            t0 = fma2(x0[10], a5v.x, t0); t1 = fma2(x0[11], a5v.y, t1);
            u0 = fma2(x1[10], a5v.x, u0); u1 = fma2(x1[11], a5v.y, u1);
            t0 = fma2(x0[12], a6v.x, t0); t1 = fma2(x0[13], a6v.y, t1);
            u0 = fma2(x1[12], a6v.x, u0); u1 = fma2(x1[13], a6v.y, u1);
            t0 = fma2(x0[14], a7v.x, t0); t1 = fma2(x0[15], a7v.y, t1);
            u0 = fma2(x1[14], a7v.x, u0); u1 = fma2(x1[15], a7v.y, u1);
            t0 = fma2(x0[16], a16, t0);
            u0 = fma2(x1[16], a16, u0);
            t0 = add2(t0, t1);
            u0 = add2(u0, u1);
            float2 fh0 = unpk(t0), fh1 = unpk(u0);
            float h0 = fmaxf(fh0.x + fh0.y + b1s[f], 0.f);
            float h1 = fmaxf(fh1.x + fh1.y + b1s[f], 0.f);
            u64 hp0 = pk(h0, h0), hp1 = pk(h1, h1);
            const ulonglong2* v2p = (const ulonglong2*)(W2s + f * 36);
            const u64*        v1p = (const u64*)(W2s + f * 36);
            ulonglong2 b0v = v2p[0], b1v = v2p[1], b2v = v2p[2], b3v = v2p[3];
            ulonglong2 b4v = v2p[4], b5v = v2p[5], b6v = v2p[6], b7v = v2p[7];
            u64 b16 = v1p[16];
            y0[0]  = fma2(hp0, b0v.x, y0[0]);   y1[0]  = fma2(hp1, b0v.x, y1[0]);
            y0[1]  = fma2(hp0, b0v.y, y0[1]);   y1[1]  = fma2(hp1, b0v.y, y1[1]);
            y0[2]  = fma2(hp0, b1v.x, y0[2]);   y1[2]  = fma2(hp1, b1v.x, y1[2]);
            y0[3]  = fma2(hp0, b1v.y, y0[3]);   y1[3]  = fma2(hp1, b1v.y, y1[3]);
            y0[4]  = fma2(hp0, b2v.x, y0[4]);   y1[4]  = fma2(hp1, b2v.x, y1[4]);
            y0[5]  = fma2(hp0, b2v.y, y0[5]);   y1[5]  = fma2(hp1, b2v.y, y1[5]);
            y0[6]  = fma2(hp0, b3v.x, y0[6]);   y1[6]  = fma2(hp1, b3v.x, y1[6]);
            y0[7]  = fma2(hp0, b3v.y, y0[7]);   y1[7]  = fma2(hp1, b3v.y, y1[7]);
            y0[8]  = fma2(hp0, b4v.x, y0[8]);   y1[8]  = fma2(hp1, b4v.x, y1[8]);
            y0[9]  = fma2(hp0, b4v.y, y0[9]);   y1[9]  = fma2(hp1, b4v.y, y1[9]);
            y0[10] = fma2(hp0, b5v.x, y0[10]);  y1[10] = fma2(hp1, b5v.x, y1[10]);
            y0[11] = fma2(hp0, b5v.y, y0[11]);  y1[11] = fma2(hp1, b5v.y, y1[11]);
            y0[12] = fma2(hp0, b6v.x, y0[12]);  y1[12] = fma2(hp1, b6v.x, y1[12]);
            y0[13] = fma2(hp0, b6v.y, y0[13]);  y1[13] = fma2(hp1, b6v.y, y1[13]);
            y0[14] = fma2(hp0, b7v.x, y0[14]);  y1[14] = fma2(hp1, b7v.x, y1[14]);
            y0[15] = fma2(hp0, b7v.y, y0[15]);  y1[15] = fma2(hp1, b7v.y, y1[15]);
            y0[16] = fma2(hp0, b16, y0[16]);    y1[16] = fma2(hp1, b16, y1[16]);
        }
        __syncthreads();
    }
    if (a0) {
        u64* yo = (u64*)(g_yp + ((size_t)blockIdx.z * S + row0) * Dm);
#pragma unroll
        for (int i = 0; i < 17; i++) yo[i] = y0[i];
    }
    if (a1) {
        u64* yo = (u64*)(g_yp + ((size_t)blockIdx.z * S + row1) * Dm);
#pragma unroll
        for (int i = 0; i < 17; i++) yo[i] = y1[i];
    }
}

// ---------------------------------------------------------------------------
// K3: FFN reduce + LN2 + layer-1 QKV fused (R11 form)
// ---------------------------------------------------------------------------
__global__ void __launch_bounds__(256) ffnred_qkv(const float* __restrict__ ipw2,
                                                  const float* __restrict__ ipb2,
                                                  const float* __restrict__ l2b,
                                                  const float* __restrict__ gg,
                                                  const float* __restrict__ bb) {
    __shared__ float xs[Dm * 32];
    __shared__ float ws[102 * Dm];
    __shared__ float bs[102];
    __shared__ __align__(16) float pre[32 * 36];
    __shared__ float l2bs[Dm], gs[Dm], bts[Dm];
    int tid = threadIdx.x;
    int row0 = blockIdx.x * 32;
    for (int i = tid; i < 102 * Dm; i += 256) ws[i] = ipw2[i];
    if (tid < 102) bs[tid] = ipb2[tid];
    if (tid < Dm) { l2bs[tid] = l2b[tid]; gs[tid] = gg[tid]; bts[tid] = bb[tid]; }
    for (int e = tid; e < 32 * 17; e += 256) {
        int r = e / 17, k = e % 17;
        int row = row0 + r;
        if (row < S) {
            u64 acc = ((const u64*)(g_x + row * Dm))[k];
#pragma unroll
            for (int g = 0; g < NFSEG; g++)
                acc = add2(acc, ((const u64*)(g_yp + ((size_t)g * S + row) * Dm))[k]);
            ((u64*)(pre + r * 36))[k] = acc;
        }
    }
    __syncthreads();
    if (tid < 32 && row0 + tid < S) {
        float y[Dm];
#pragma unroll
        for (int d = 0; d < Dm; d++) y[d] = pre[tid * 36 + d] + l2bs[d];
        float m = 0.f;
#pragma unroll
        for (int d = 0; d < Dm; d++) m += y[d];
        m *= (1.0f / Dm);
        float v = 0.f;
#pragma unroll
        for (int d = 0; d < Dm; d++) { float tt = y[d] - m; v = fmaf(tt, tt, v); }
        v *= (1.0f / Dm);
        float inv = rsqrtf(v + EPSV);
        int row = row0 + tid;
#pragma unroll
        for (int d = 0; d < Dm; d++) {
            float xv = (y[d] - m) * inv * gs[d] + bts[d];
            xs[d * 32 + tid] = xv;
            g_x[row * Dm + d] = xv;
        }
    }
    __syncthreads();
    const float scale = rsqrtf(17.f);
    int lane = tid & 31, w = tid >> 5;
    int s = row0 + lane;
    for (int cc = w; cc < 102; cc += 8) {
        float acc = bs[cc];
        const float* wp = ws + cc * Dm;
#pragma unroll
        for (int d = 0; d < Dm; d++) acc = fmaf(xs[d * 32 + lane], wp[d], acc);
        if (s < S) {
            int kind = cc / Dm;
            int c2 = cc % Dm;
            int h = c2 / HD, dd = c2 % HD;
            int off = (h * S + s) * PH + dd;
            if (kind == 0)      g_q[off] = acc * scale;
            else if (kind == 1) g_k[off] = acc;
            else                g_v[off] = acc;
        }
    }
}

// ---------------------------------------------------------------------------
// K4 (fused agent tail, R11 P1 form)
// ---------------------------------------------------------------------------
__global__ void __launch_bounds__(256) agent_tail(
    const float* __restrict__ opw2, const float* __restrict__ opb2,
    const float* __restrict__ g12,  const float* __restrict__ b12,
    const float* __restrict__ l1w2, const float* __restrict__ l1b2,
    const float* __restrict__ l2w2, const float* __restrict__ l2b2,
    const float* __restrict__ g22,  const float* __restrict__ b22,
    float* __restrict__ out)
{
    __shared__ __align__(16) float sm[4800];
    int tid = threadIdx.x;
    int b = blockIdx.x;
    unsigned ls = 0;

    {
        int h = b / NSEG2;
        int seg = b % NSEG2;
        int k0 = seg * KSEG2;
        int n = min(KSEG2, S - k0);
        float* Ks = sm;
        float* Vs = sm + 1800;
        const float4* ksrc = (const float4*)(g_k + (h * S + k0) * PH);
        const float4* vsrc = (const float4*)(g_v + (h * S + k0) * PH);
        float4* kdst = (float4*)Ks; float4* vdst = (float4*)Vs;
        for (int i = tid; i < n * 5; i += 256) { kdst[i] = ksrc[i]; vdst[i] = vsrc[i]; }
        __syncthreads();
        if (tid < HW) {
            int start = g_agent * HW;
            u64 q[9], acc[9];
            const u64* qp = (const u64*)(g_q + (h * S + start + tid) * PH);
#pragma unroll
            for (int i = 0; i < 9; i++) { q[i] = qp[i]; acc[i] = 0ULL; }
            float ssum = 0.f;
            const ulonglong2* K2 = (const ulonglong2*)Ks;
            const ulonglong2* V2 = (const ulonglong2*)Vs;
            for (int kk = 0; kk < n; kk++) {
                ulonglong2 ka = K2[0], kb = K2[1], kc = K2[2], kd = K2[3];
                u64 ke = K2[4].x;
                u64 t0 = mul2(q[0], ka.x),  t1 = mul2(q[1], ka.y);
                t0 = fma2(q[2], kb.x, t0);  t1 = fma2(q[3], kb.y, t1);
                t0 = fma2(q[4], kc.x, t0);  t1 = fma2(q[5], kc.y, t1);
                t0 = fma2(q[6], kd.x, t0);  t1 = fma2(q[7], kd.y, t1);
                t0 = fma2(q[8], ke, t0);
                t0 = add2(t0, t1);
                float2 f = unpk(t0);
                float p = __expf(f.x + f.y);
                ssum += p;
                u64 pp = pk(p, p);
                ulonglong2 va = V2[0], vb = V2[1], vc = V2[2], vd = V2[3];
                u64 ve = V2[4].x;
                acc[0] = fma2(pp, va.x, acc[0]); acc[1] = fma2(pp, va.y, acc[1]);
                acc[2] = fma2(pp, vb.x, acc[2]); acc[3] = fma2(pp, vb.y, acc[3]);
                acc[4] = fma2(pp, vc.x, acc[4]); acc[5] = fma2(pp, vc.y, acc[5]);
                acc[6] = fma2(pp, vd.x, acc[6]); acc[7] = fma2(pp, vd.y, acc[7]);
                acc[8] = fma2(pp, ve, acc[8]);
                K2 += 5; V2 += 5;
            }
            u64* pa = (u64*)(g_pacca + ((h * NSEG2 + seg) * HW + tid) * PAC);
#pragma unroll
            for (int i = 0; i < 9; i++) pa[i] = acc[i];
            g_psuma[(h * NSEG2 + seg) * HW + tid] = ssum;
        }
    }
    gsync(ls);  // 1

    {
        int e = b * 256 + tid;
        if (b < 11 && e < HW * Dm) {
            int r = e / Dm, c = e % Dm;
            int h = c / HD, d = c % HD;
            float a = 0.f, smm = 0.f;
#pragma unroll 4
            for (int g = 0; g < NSEG2; g++) {
                a   += g_pacca[((h * NSEG2 + g) * HW + r) * PAC + d];
                smm += g_psuma[(h * NSEG2 + g) * HW + r];
            }
            g_oa[e] = a / smm;
        }
    }
    gsync(ls);  // 2

    if (b == 0) {
        float* ws  = sm;
        float* bs  = sm + 1156;
        float* gs  = sm + 1190;
        float* bts = sm + 1224;
        for (int i = tid; i < Dm * Dm; i += 256) ws[i] = opw2[i];
        if (tid < Dm) { bs[tid] = opb2[tid]; gs[tid] = g12[tid]; bts[tid] = b12[tid]; }
        __syncthreads();
        if (tid < HW) {
            int s = g_agent * HW + tid;
            float orow[Dm], y[Dm];
#pragma unroll
            for (int d = 0; d < Dm; d++) orow[d] = g_oa[tid * Dm + d];
#pragma unroll 2
            for (int d = 0; d < Dm; d++) {
                float a = bs[d] + g_x[s * Dm + d];
                const float* wp = ws + d * Dm;
#pragma unroll
                for (int k = 0; k < Dm; k++) a = fmaf(orow[k], wp[k], a);
                y[d] = a;
            }
            float m = 0.f;
#pragma unroll
            for (int d = 0; d < Dm; d++) m += y[d];
            m *= (1.0f / Dm);
            float v = 0.f;
#pragma unroll
            for (int d = 0; d < Dm; d++) { float tt = y[d] - m; v = fmaf(tt, tt, v); }
            v *= (1.0f / Dm);
            float inv = rsqrtf(v + EPSV);
#pragma unroll
            for (int d = 0; d < Dm; d++) g_xa[tid * Dm + d] = (y[d] - m) * inv * gs[d] + bts[d];
        }
    }
    gsync(ls);  // 3

    if (b < NFSEG2) {
        float* W1s = sm;
        float* W2s = sm + 2304;
        float* b1s = sm + 4608;
        int fbase = b * FSEG2;
        for (int e = tid; e < FSEG2 * Dm; e += 256) {
            int f = e / Dm, d = e % Dm;
            W1s[f * 36 + d] = l1w2[(fbase + f) * Dm + d];
            W2s[f * 36 + d] = l2w2[d * FFd + fbase + f];
        }
        if (tid < FSEG2) b1s[tid] = l1b2[fbase + tid];
        __syncthreads();
        if (tid < HW) {
            u64 xr[17], y[17];
            const u64* p = (const u64*)(g_xa + tid * Dm);
#pragma unroll
            for (int i = 0; i < 17; i++) { xr[i] = p[i]; y[i] = 0ULL; }
#pragma unroll 2
            for (int f = 0; f < FSEG2; f++) {
                const ulonglong2* w2p = (const ulonglong2*)(W1s + f * 36);
                const u64*        w1p = (const u64*)(W1s + f * 36);
                ulonglong2 a0 = w2p[0], a1 = w2p[1], a2 = w2p[2], a3 = w2p[3];
                ulonglong2 a4 = w2p[4], a5 = w2p[5], a6 = w2p[6], a7 = w2p[7];
                u64 a16 = w1p[16];
                u64 t0 = mul2(xr[0], a0.x),  t1 = mul2(xr[1], a0.y);
                t0 = fma2(xr[2], a1.x, t0);  t1 = fma2(xr[3], a1.y, t1);
                t0 = fma2(xr[4], a2.x, t0);  t1 = fma2(xr[5], a2.y, t1);
                t0 = fma2(xr[6], a3.x, t0);  t1 = fma2(xr[7], a3.y, t1);
                t0 = fma2(xr[8], a4.x, t0);  t1 = fma2(xr[9], a4.y, t1);
                t0 = fma2(xr[10], a5.x, t0); t1 = fma2(xr[11], a5.y, t1);
                t0 = fma2(xr[12], a6.x, t0); t1 = fma2(xr[13], a6.y, t1);
                t0 = fma2(xr[14], a7.x, t0); t1 = fma2(xr[15], a7.y, t1);
                t0 = fma2(xr[16], a16, t0);
                t0 = add2(t0, t1);
                float2 fh = unpk(t0);
                float hrelu = fmaxf(fh.x + fh.y + b1s[f], 0.f);
                u64 hp = pk(hrelu, hrelu);
                const ulonglong2* v2p = (const ulonglong2*)(W2s + f * 36);
                const u64*        v1p = (const u64*)(W2s + f * 36);
                ulonglong2 b0 = v2p[0], b1v = v2p[1], b2v = v2p[2], b3 = v2p[3];
                ulonglong2 b4 = v2p[4], b5 = v2p[5], b6 = v2p[6], b7 = v2p[7];
                u64 b16 = v1p[16];
                y[0]  = fma2(hp, b0.x, y[0]);   y[1]  = fma2(hp, b0.y, y[1]);
                y[2]  = fma2(hp, b1v.x, y[2]);  y[3]  = fma2(hp, b1v.y, y[3]);
                y[4]  = fma2(hp, b2v.x, y[4]);  y[5]  = fma2(hp, b2v.y, y[5]);
                y[6]  = fma2(hp, b3.x, y[6]);   y[7]  = fma2(hp, b3.y, y[7]);
                y[8]  = fma2(hp, b4.x, y[8]);   y[9]  = fma2(hp, b4.y, y[9]);
                y[10] = fma2(hp, b5.x, y[10]);  y[11] = fma2(hp, b5.y, y[11]);
                y[12] = fma2(hp, b6.x, y[12]);  y[13] = fma2(hp, b6.y, y[13]);
                y[14] = fma2(hp, b7.x, y[14]);  y[15] = fma2(hp, b7.y, y[15]);
                y[16] = fma2(hp, b16, y[16]);
            }
            u64* yo = (u64*)(g_ypa + ((size_t)b * HW + tid) * Dm);
#pragma unroll
            for (int i = 0; i < 17; i++) yo[i] = y[i];
        }
    }
    gsync(ls);  // 4

    if (b == 0) {
        float* rows = sm;
        if (tid < HW) {
            float y[Dm];
#pragma unroll
            for (int d = 0; d < Dm; d++) y[d] = g_xa[tid * Dm + d] + l2b2[d];
            for (int g = 0; g < NFSEG2; g++) {
                const float* yp = g_ypa + ((size_t)g * HW + tid) * Dm;
#pragma unroll
                for (int d = 0; d < Dm; d++) y[d] += yp[d];
            }
            float m = 0.f;
#pragma unroll
            for (int d = 0; d < Dm; d++) m += y[d];
            m *= (1.0f / Dm);
            float v = 0.f;
#pragma unroll
            for (int d = 0; d < Dm; d++) { float tt = y[d] - m; v = fmaf(tt, tt, v); }
            v *= (1.0f / Dm);
            float inv = rsqrtf(v + EPSV);
#pragma unroll
            for (int d = 0; d < Dm; d++) rows[tid * Dm + d] = (y[d] - m) * inv * g22[d] + b22[d];
        }
        __syncthreads();
        if (tid < Dm) {
            float s = 0.f;
            for (int r = 0; r < HW; r++) s += rows[r * Dm + tid];
            out[tid] = s * (1.0f / 81.0f);
        }
    }
}

// ---------------------------------------------------------------------------
extern "C" void kernel_launch(void* const* d_in, const int* in_sizes, int n_in,
                              void* d_out, int out_size) {
    const float* obs = (const float*)d_in[0];
    const float* c1w = (const float*)d_in[1];
    const float* c1b = (const float*)d_in[2];
    const float* c2w = (const float*)d_in[3];
    const float* c2b = (const float*)d_in[4];
    const float* ipw = (const float*)d_in[5];
    const float* ipb = (const float*)d_in[6];
    const float* opw = (const float*)d_in[7];
    const float* opb = (const float*)d_in[8];
    const float* l1w = (const float*)d_in[9];
    const float* l1b = (const float*)d_in[10];
    const float* l2w = (const float*)d_in[11];
    const float* l2b = (const float*)d_in[12];
    const float* g1  = (const float*)d_in[13];
    const float* b1  = (const float*)d_in[14];
    const float* g2  = (const float*)d_in[15];
    const float* b2  = (const float*)d_in[16];
    float* out = (float*)d_out;

    layer0_pre<<<148, 512>>>(obs, c1w, c1b, c2w, c2b, ipw, ipb, opw, opb, g1, b1);
    ffn0<<<dim3((S + 127) / 128, 1, NFSEG), 64>>>(l1w, l1b, l2w);
    ffnred_qkv<<<(S + 31) / 32, 256>>>(ipw + 102 * Dm, ipb + 102, l2b, g2, b2);
    agent_tail<<<148, 256>>>(opw + Dm * Dm, opb + Dm, g1 + Dm, b1 + Dm,
                             l1w + FFd * Dm, l1b + FFd, l2w + Dm * FFd, l2b + Dm,
                             g2 + Dm, b2 + Dm, out);
}

// round 14
// speedup vs baseline: 1.2626x; 1.2626x over previous
#include <cuda_runtime.h>

#define S      6561
#define Dm     34
#define HD     17
#define PH     20
#define PAC    18
#define FFd    2048
#define NH     2
#define HW     81
#define EPSV   1e-5f
#define ESTR   (NH * HW * HW)
// layer-0 FFN tiling: 16 f-segments of 128, 2 rows/thread, 64-thread blocks
#define NFSEG  16
#define FSEG   128
#define FCHK0  64
// layer-1 agent attention: 2 heads x 74 segs = 148 blocks
#define NSEG2  74
#define KSEG2  89
// agent FFN split
#define NFSEG2 32
#define FSEG2  64

typedef unsigned long long u64;

// ---- packed fp32 helpers ----
__device__ __forceinline__ u64 fma2(u64 a, u64 b, u64 c) {
    u64 d; asm("fma.rn.f32x2 %0, %1, %2, %3;" : "=l"(d) : "l"(a), "l"(b), "l"(c)); return d;
}
__device__ __forceinline__ u64 mul2(u64 a, u64 b) {
    u64 d; asm("mul.rn.f32x2 %0, %1, %2;" : "=l"(d) : "l"(a), "l"(b)); return d;
}
__device__ __forceinline__ u64 add2(u64 a, u64 b) {
    u64 d; asm("add.rn.f32x2 %0, %1, %2;" : "=l"(d) : "l"(a), "l"(b)); return d;
}
__device__ __forceinline__ float2 unpk(u64 v) {
    float2 f; asm("mov.b64 {%0, %1}, %2;" : "=f"(f.x), "=f"(f.y) : "l"(v)); return f;
}
__device__ __forceinline__ u64 pk(float x, float y) {
    u64 v; asm("mov.b64 %0, {%1, %2};" : "=l"(v) : "f"(x), "f"(y)); return v;
}

// ---- device-global scratch ----
__device__ unsigned g_cnt;
__device__ unsigned g_sense;
__device__ int   g_agent;
__device__ __align__(16) float g_emb[HW * 16];
__device__ __align__(16) float g_x[S * Dm];
__device__ __align__(16) float g_q[NH * S * PH];
__device__ __align__(16) float g_k[NH * S * PH];
__device__ __align__(16) float g_v[NH * S * PH];
__device__ __align__(16) float g_o[S * Dm];
__device__ __align__(16) float g_yp[NFSEG * S * Dm];
__device__ __align__(16) float g_QA[NH * HW * HD];
__device__ __align__(16) float g_QB[NH * HW * HD];
__device__ __align__(16) float g_KA[NH * HW * HD];
__device__ __align__(16) float g_KB[NH * HW * HD];
__device__ __align__(16) float g_VA[NH * HW * HD];
__device__ __align__(16) float g_VB[NH * HW * HD];
__device__ __align__(16) float g_E[4 * ESTR];    // EA, EB row-major; EC, ED TRANSPOSED
__device__ __align__(16) float g_pacca[NH * NSEG2 * HW * PAC];
__device__ float g_psuma[NH * NSEG2 * HW];
__device__ __align__(16) float g_xa[HW * Dm];
__device__ __align__(16) float g_ypa[NFSEG2 * HW * Dm];
__device__ __align__(16) float g_oa[HW * Dm];

// ---- sense-reversing grid barrier (all blocks resident) ----
__device__ __forceinline__ void gsync(unsigned& ls) {
    __syncthreads();
    if (threadIdx.x == 0) {
        unsigned ns = ls ^ 1u;
        __threadfence();
        unsigned old = atomicAdd(&g_cnt, 1u);
        if (old == gridDim.x - 1u) {
            g_cnt = 0u;
            __threadfence();
            atomicExch(&g_sense, ns);
        } else {
            while (atomicAdd(&g_sense, 0u) != ns) { __nanosleep(64); }
        }
        ls = ns;
        __threadfence();
    }
    __syncthreads();
}

// ---------------------------------------------------------------------------
// K1 (fused front): conv+argmax -> basis QKV -> exp(logits). grid 148x256.
// ---------------------------------------------------------------------------
__global__ void __launch_bounds__(256) front(
    const float* __restrict__ obs,
    const float* __restrict__ c1w, const float* __restrict__ c1b,
    const float* __restrict__ c2w, const float* __restrict__ c2b,
    const float* __restrict__ ipw, const float* __restrict__ ipb)
{
    __shared__ float so[192];
    __shared__ float c1s[1296];
    int tid = threadIdx.x;
    int b = blockIdx.x;
    unsigned ls = 0;

    if (b == 0) {
        for (int i = tid; i < 162; i += 256) so[i] = obs[i];
        __syncthreads();
        if (tid == 0) {
            float mx = so[0]; int mi = 0;
            for (int i = 1; i < 81; i++) if (so[i] > mx) { mx = so[i]; mi = i; }
            g_agent = mi;
        }
        for (int idx = tid; idx < 16 * 81; idx += 256) {
            int ch = idx / 81, pos = idx % 81, r = pos / 9, c = pos % 9;
            float acc = c1b[ch];
            for (int ci = 0; ci < 2; ci++)
                for (int dr = 0; dr < 3; dr++) {
                    int rr = r + dr - 1; if (rr < 0 || rr >= 9) continue;
                    for (int dc = 0; dc < 3; dc++) {
                        int cc = c + dc - 1; if (cc < 0 || cc >= 9) continue;
                        acc += so[ci * 81 + rr * 9 + cc] * c1w[((ch * 2 + ci) * 3 + dr) * 3 + dc];
                    }
                }
            c1s[idx] = fmaxf(acc, 0.f);
        }
        __syncthreads();
        for (int idx = tid; idx < 16 * 81; idx += 256) {
            int ch = idx / 81, pos = idx % 81, r = pos / 9, c = pos % 9;
            float acc = c2b[ch];
            for (int ci = 0; ci < 16; ci++)
                for (int dr = 0; dr < 3; dr++) {
                    int rr = r + dr - 1; if (rr < 0 || rr >= 9) continue;
                    for (int dc = 0; dc < 3; dc++) {
                        int cc = c + dc - 1; if (cc < 0 || cc >= 9) continue;
                        acc += c1s[ci * 81 + rr * 9 + cc] * c2w[((ch * 16 + ci) * 3 + dr) * 3 + dc];
                    }
                }
            g_emb[pos * 16 + ch] = fmaxf(acc, 0.f);
        }
    }
    gsync(ls);  // 1

    for (int idx = b * 256 + tid; idx < 162 * 102; idx += 148 * 256) {
        int v = idx / 102, c = idx % 102;
        const float* wr = ipw + c * Dm;
        float acc;
        if (v < 81) {
            int i = v;
            acc = ipb[c];
#pragma unroll
            for (int d = 0; d < 16; d++) acc = fmaf(g_emb[i * 16 + d], wr[d], acc);
            acc = fmaf((float)(i / 9) * 0.25f, wr[32], acc);
            acc = fmaf((float)(i % 9) * 0.25f, wr[33], acc);
        } else {
            int j = v - 81;
            acc = 0.f;
#pragma unroll
            for (int d = 0; d < 16; d++) acc = fmaf(g_emb[j * 16 + d], wr[16 + d], acc);
            acc = fmaf(-(float)(j / 9) * 0.25f, wr[32], acc);
            acc = fmaf(-(float)(j % 9) * 0.25f, wr[33], acc);
        }
        int kind = c / Dm;
        int cc = c % Dm;
        int h = cc / HD, dd = cc % HD;
        int off = (h * HW + (v % 81)) * HD + dd;
        if (kind == 0) {
            float sv = acc * rsqrtf(17.f);
            if (v < 81) g_QA[off] = sv; else g_QB[off] = sv;
        } else if (kind == 1) {
            if (v < 81) g_KA[off] = acc; else g_KB[off] = acc;
        } else {
            if (v < 81) g_VA[off] = acc; else g_VB[off] = acc;
        }
    }
    gsync(ls);  // 2

    for (int idx = b * 256 + tid; idx < 4 * ESTR; idx += 148 * 256) {
        int p = idx / ESTR;
        int r = idx % ESTR;
        int h = r / (HW * HW);
        int q2 = r % (HW * HW);
        int i = q2 / HW, m = q2 % HW;
        const float* L;
        const float* R;
        if (p == 0)      { L = g_QA + (h * HW + i) * HD; R = g_KA + (h * HW + m) * HD; }
        else if (p == 1) { L = g_QA + (h * HW + i) * HD; R = g_KB + (h * HW + m) * HD; }
        else if (p == 2) { L = g_KA + (h * HW + i) * HD; R = g_QB + (h * HW + m) * HD; }
        else             { L = g_KB + (h * HW + i) * HD; R = g_QB + (h * HW + m) * HD; }
        float dot = 0.f;
#pragma unroll
        for (int d = 0; d < HD; d++) dot = fmaf(L[d], R[d], dot);
        g_E[idx] = __expf(dot);
    }
}

// ---------------------------------------------------------------------------
// K2: structured attention -> g_o (EC/ED transposed, coalesced)
// ---------------------------------------------------------------------------
__global__ void __launch_bounds__(512) attn_struct() {
    __shared__ float sea[HW], seb[HW];
    __shared__ __align__(16) float sva[HW * 18];
    __shared__ __align__(16) float svb[HW * 18];
    __shared__ float psum[4 * HW];
    __shared__ __align__(16) u64 pacc[4 * HW * 9];
    int tid = threadIdx.x;
    int i = blockIdx.x, h = blockIdx.y;
    for (int t = tid; t < HW; t += 512) {
        sea[t] = g_E[0 * ESTR + (h * HW + i) * HW + t];
        seb[t] = g_E[1 * ESTR + (h * HW + i) * HW + t];
    }
    for (int t = tid; t < HW * 18; t += 512) {
        int m = t / 18, d = t % 18;
        sva[t] = (d < HD) ? g_VA[(h * HW + m) * HD + d] : 0.f;
        svb[t] = (d < HD) ? g_VB[(h * HW + m) * HD + d] : 0.f;
    }
    __syncthreads();
    int quad = tid >> 7;
    int j = tid & 127;
    if (j < HW) {
        bool isA = quad < 2;
        int lo = (quad & 1) ? 41 : 0;
        int hi = (quad & 1) ? HW : 41;
        const float* et = g_E + (isA ? 2 : 3) * ESTR + h * HW * HW + j;
        const float* se = isA ? sea : seb;
        const float* sv = isA ? sva : svb;
        float z = 0.f;
        u64 w[9];
#pragma unroll
        for (int k = 0; k < 9; k++) w[k] = 0ULL;
#pragma unroll 4
        for (int m = lo; m < hi; m++) {
            float f = se[m] * et[m * HW];
            z += f;
            u64 fp = pk(f, f);
            const u64* vr = (const u64*)(sv + m * 18);
#pragma unroll
            for (int k = 0; k < 9; k++) w[k] = fma2(fp, vr[k], w[k]);
        }
        psum[quad * HW + j] = z;
        u64* pw = pacc + (quad * HW + j) * 9;
#pragma unroll
        for (int k = 0; k < 9; k++) pw[k] = w[k];
    }
    __syncthreads();
    if (tid < HW) {
        int jj = tid;
        float zm = psum[jj] + psum[HW + jj];
        float zn = psum[2 * HW + jj] + psum[3 * HW + jj];
        const u64* p0 = pacc + jj * 9;
        const u64* p1 = pacc + (HW + jj) * 9;
        const u64* p2 = pacc + (2 * HW + jj) * 9;
        const u64* p3 = pacc + (3 * HW + jj) * 9;
        float inv = 1.0f / (zm * zn);
        float* od = g_o + (i * HW + jj) * Dm + h * HD;
#pragma unroll
        for (int k = 0; k < 9; k++) {
            float2 A = unpk(add2(p0[k], p1[k]));
            float2 B = unpk(add2(p2[k], p3[k]));
            int d = 2 * k;
            od[d] = (A.x * zn + B.x * zm) * inv;
            if (d + 1 < HD) od[d + 1] = (A.y * zn + B.y * zm) * inv;
        }
    }
}

// ---------------------------------------------------------------------------
// K3: tokens + out_proj + residual + LN1 -> g_x
// ---------------------------------------------------------------------------
__global__ void __launch_bounds__(128) tokens_proj_ln(const float* __restrict__ opw,
                                                      const float* __restrict__ opb,
                                                      const float* __restrict__ gg,
                                                      const float* __restrict__ bb) {
    __shared__ float embs[1296];
    __shared__ float ws[Dm * Dm];
    __shared__ float bs[Dm], gs[Dm], bts[Dm];
    __shared__ float ys[64 * 36];
    int tid = threadIdx.x;
    for (int i = tid; i < 1296; i += 128) embs[i] = g_emb[i];
    for (int i = tid; i < Dm * Dm; i += 128) ws[i] = opw[i];
    if (tid < Dm) { bs[tid] = opb[tid]; gs[tid] = gg[tid]; bts[tid] = bb[tid]; }
    __syncthreads();
    int half = tid >> 6;
    int lt = tid & 63;
    int t = blockIdx.x * 64 + lt;
    if (t < S) {
        int i = t / HW, j = t % HW;
        float orow[Dm];
#pragma unroll
        for (int d = 0; d < Dm; d++) orow[d] = g_o[t * Dm + d];
        int dlo = half * 17;
#pragma unroll 1
        for (int d = dlo; d < dlo + 17; d++) {
            float xv;
            if (d < 16)       xv = embs[i * 16 + d];
            else if (d < 32)  xv = embs[j * 16 + (d - 16)];
            else if (d == 32) xv = ((float)(i / 9) - (float)(j / 9)) * 0.25f;
            else              xv = ((float)(i % 9) - (float)(j % 9)) * 0.25f;
            float a = bs[d] + xv;
            const float* wp = ws + d * Dm;
#pragma unroll
            for (int k = 0; k < Dm; k++) a = fmaf(orow[k], wp[k], a);
            ys[lt * 36 + d] = a;
        }
    }
    __syncthreads();
    if (half == 0 && t < S) {
        float y[Dm];
#pragma unroll
        for (int d = 0; d < Dm; d++) y[d] = ys[lt * 36 + d];
        float m = 0.f;
#pragma unroll
        for (int d = 0; d < Dm; d++) m += y[d];
        m *= (1.0f / Dm);
        float v = 0.f;
#pragma unroll
        for (int d = 0; d < Dm; d++) { float tt = y[d] - m; v = fmaf(tt, tt, v); }
        v *= (1.0f / Dm);
        float inv = rsqrtf(v + EPSV);
#pragma unroll
        for (int d = 0; d < Dm; d++) g_x[t * Dm + d] = (y[d] - m) * inv * gs[d] + bts[d];
    }
}

// ---------------------------------------------------------------------------
// K4: layer-0 FFN partials — 2 rows/thread, 64-thread blocks, 6 blocks/SM
// (888 slots >= 832 blocks -> single wave). grid (52, 1, 16).
// ---------------------------------------------------------------------------
__global__ void __launch_bounds__(64, 6) ffn0(const float* __restrict__ l1w,
                                              const float* __restrict__ l1b,
                                              const float* __restrict__ l2w) {
    __shared__ __align__(16) float W1s[FCHK0 * 36];
    __shared__ __align__(16) float W2s[FCHK0 * 36];
    __shared__ float b1s[FCHK0];
    int tid = threadIdx.x;
    int row0 = blockIdx.x * 128 + tid;
    int row1 = row0 + 64;
    int fbase = blockIdx.z * FSEG;
    bool a0 = row0 < S, a1 = row1 < S;
    u64 x0[17], x1[17], y0[17], y1[17];
#pragma unroll
    for (int i = 0; i < 17; i++) { x0[i] = 0ULL; x1[i] = 0ULL; y0[i] = 0ULL; y1[i] = 0ULL; }
    if (a0) {
        const u64* p = (const u64*)(g_x + row0 * Dm);
#pragma unroll
        for (int i = 0; i < 17; i++) x0[i] = p[i];
    }
    if (a1) {
        const u64* p = (const u64*)(g_x + row1 * Dm);
#pragma unroll
        for (int i = 0; i < 17; i++) x1[i] = p[i];
    }
    for (int fc = fbase; fc < fbase + FSEG; fc += FCHK0) {
        for (int e = tid; e < FCHK0 * Dm; e += 64) {
            int f = e / Dm, d = e % Dm;
            W1s[f * 36 + d] = l1w[(fc + f) * Dm + d];
            W2s[f * 36 + d] = l2w[d * FFd + fc + f];
        }
        if (tid < FCHK0) b1s[tid] = l1b[fc + tid];
        __syncthreads();
#pragma unroll 2
        for (int f = 0; f < FCHK0; f++) {
            const ulonglong2* w2p = (const ulonglong2*)(W1s + f * 36);
            const u64*        w1p = (const u64*)(W1s + f * 36);
            ulonglong2 a0v = w2p[0], a1v = w2p[1], a2v = w2p[2], a3v = w2p[3];
            ulonglong2 a4v = w2p[4], a5v = w2p[5], a6v = w2p[6], a7v = w2p[7];
            u64 a16 = w1p[16];
            u64 t0 = mul2(x0[0], a0v.x),  t1 = mul2(x0[1], a0v.y);
            u64 u0 = mul2(x1[0], a0v.x),  u1 = mul2(x1[1], a0v.y);
            t0 = fma2(x0[2], a1v.x, t0);  t1 = fma2(x0[3], a1v.y, t1);
            u0 = fma2(x1[2], a1v.x, u0);  u1 = fma2(x1[3], a1v.y, u1);
            t0 = fma2(x0[4], a2v.x, t0);  t1 = fma2(x0[5], a2v.y, t1);
            u0 = fma2(x1[4], a2v.x, u0);  u1 = fma2(x1[5], a2v.y, u1);
            t0 = fma2(x0[6], a3v.x, t0);  t1 = fma2(x0[7], a3v.y, t1);
            u0 = fma2(x1[6], a3v.x, u0);  u1 = fma2(x1[7], a3v.y, u1);
            t0 = fma2(x0[8], a4v.x, t0);  t1 = fma2(x0[9], a4v.y, t1);
            u0 = fma2(x1[8], a4v.x, u0);  u1 = fma2(x1[9], a4v.y, u1);
            t0 = fma2(x0[10], a5v.x, t0); t1 = fma2(x0[11], a5v.y, t1);
            u0 = fma2(x1[10], a5v.x, u0); u1 = fma2(x1[11], a5v.y, u1);
            t0 = fma2(x0[12], a6v.x, t0); t1 = fma2(x0[13], a6v.y, t1);
            u0 = fma2(x1[12], a6v.x, u0); u1 = fma2(x1[13], a6v.y, u1);
            t0 = fma2(x0[14], a7v.x, t0); t1 = fma2(x0[15], a7v.y, t1);
            u0 = fma2(x1[14], a7v.x, u0); u1 = fma2(x1[15], a7v.y, u1);
            t0 = fma2(x0[16], a16, t0);
            u0 = fma2(x1[16], a16, u0);
            t0 = add2(t0, t1);
            u0 = add2(u0, u1);
            float2 fh0 = unpk(t0), fh1 = unpk(u0);
            float h0 = fmaxf(fh0.x + fh0.y + b1s[f], 0.f);
            float h1 = fmaxf(fh1.x + fh1.y + b1s[f], 0.f);
            u64 hp0 = pk(h0, h0), hp1 = pk(h1, h1);
            const ulonglong2* v2p = (const ulonglong2*)(W2s + f * 36);
            const u64*        v1p = (const u64*)(W2s + f * 36);
            ulonglong2 b0v = v2p[0], b1v = v2p[1], b2v = v2p[2], b3v = v2p[3];
            ulonglong2 b4v = v2p[4], b5v = v2p[5], b6v = v2p[6], b7v = v2p[7];
            u64 b16 = v1p[16];
            y0[0]  = fma2(hp0, b0v.x, y0[0]);   y1[0]  = fma2(hp1, b0v.x, y1[0]);
            y0[1]  = fma2(hp0, b0v.y, y0[1]);   y1[1]  = fma2(hp1, b0v.y, y1[1]);
            y0[2]  = fma2(hp0, b1v.x, y0[2]);   y1[2]  = fma2(hp1, b1v.x, y1[2]);
            y0[3]  = fma2(hp0, b1v.y, y0[3]);   y1[3]  = fma2(hp1, b1v.y, y1[3]);
            y0[4]  = fma2(hp0, b2v.x, y0[4]);   y1[4]  = fma2(hp1, b2v.x, y1[4]);
            y0[5]  = fma2(hp0, b2v.y, y0[5]);   y1[5]  = fma2(hp1, b2v.y, y1[5]);
            y0[6]  = fma2(hp0, b3v.x, y0[6]);   y1[6]  = fma2(hp1, b3v.x, y1[6]);
            y0[7]  = fma2(hp0, b3v.y, y0[7]);   y1[7]  = fma2(hp1, b3v.y, y1[7]);
            y0[8]  = fma2(hp0, b4v.x, y0[8]);   y1[8]  = fma2(hp1, b4v.x, y1[8]);
            y0[9]  = fma2(hp0, b4v.y, y0[9]);   y1[9]  = fma2(hp1, b4v.y, y1[9]);
            y0[10] = fma2(hp0, b5v.x, y0[10]);  y1[10] = fma2(hp1, b5v.x, y1[10]);
            y0[11] = fma2(hp0, b5v.y, y0[11]);  y1[11] = fma2(hp1, b5v.y, y1[11]);
            y0[12] = fma2(hp0, b6v.x, y0[12]);  y1[12] = fma2(hp1, b6v.x, y1[12]);
            y0[13] = fma2(hp0, b6v.y, y0[13]);  y1[13] = fma2(hp1, b6v.y, y1[13]);
            y0[14] = fma2(hp0, b7v.x, y0[14]);  y1[14] = fma2(hp1, b7v.x, y1[14]);
            y0[15] = fma2(hp0, b7v.y, y0[15]);  y1[15] = fma2(hp1, b7v.y, y1[15]);
            y0[16] = fma2(hp0, b16, y0[16]);    y1[16] = fma2(hp1, b16, y1[16]);
        }
        __syncthreads();
    }
    if (a0) {
        u64* yo = (u64*)(g_yp + ((size_t)blockIdx.z * S + row0) * Dm);
#pragma unroll
        for (int i = 0; i < 17; i++) yo[i] = y0[i];
    }
    if (a1) {
        u64* yo = (u64*)(g_yp + ((size_t)blockIdx.z * S + row1) * Dm);
#pragma unroll
        for (int i = 0; i < 17; i++) yo[i] = y1[i];
    }
}

// ---------------------------------------------------------------------------
// K5: FFN reduce + LN2 + layer-1 QKV fused (R11 form)
// ---------------------------------------------------------------------------
__global__ void __launch_bounds__(256) ffnred_qkv(const float* __restrict__ ipw2,
                                                  const float* __restrict__ ipb2,
                                                  const float* __restrict__ l2b,
                                                  const float* __restrict__ gg,
                                                  const float* __restrict__ bb) {
    __shared__ float xs[Dm * 32];
    __shared__ float ws[102 * Dm];
    __shared__ float bs[102];
    __shared__ __align__(16) float pre[32 * 36];
    __shared__ float l2bs[Dm], gs[Dm], bts[Dm];
    int tid = threadIdx.x;
    int row0 = blockIdx.x * 32;
    for (int i = tid; i < 102 * Dm; i += 256) ws[i] = ipw2[i];
    if (tid < 102) bs[tid] = ipb2[tid];
    if (tid < Dm) { l2bs[tid] = l2b[tid]; gs[tid] = gg[tid]; bts[tid] = bb[tid]; }
    for (int e = tid; e < 32 * 17; e += 256) {
        int r = e / 17, k = e % 17;
        int row = row0 + r;
        if (row < S) {
            u64 acc = ((const u64*)(g_x + row * Dm))[k];
#pragma unroll
            for (int g = 0; g < NFSEG; g++)
                acc = add2(acc, ((const u64*)(g_yp + ((size_t)g * S + row) * Dm))[k]);
            ((u64*)(pre + r * 36))[k] = acc;
        }
    }
    __syncthreads();
    if (tid < 32 && row0 + tid < S) {
        float y[Dm];
#pragma unroll
        for (int d = 0; d < Dm; d++) y[d] = pre[tid * 36 + d] + l2bs[d];
        float m = 0.f;
#pragma unroll
        for (int d = 0; d < Dm; d++) m += y[d];
        m *= (1.0f / Dm);
        float v = 0.f;
#pragma unroll
        for (int d = 0; d < Dm; d++) { float tt = y[d] - m; v = fmaf(tt, tt, v); }
        v *= (1.0f / Dm);
        float inv = rsqrtf(v + EPSV);
        int row = row0 + tid;
#pragma unroll
        for (int d = 0; d < Dm; d++) {
            float xv = (y[d] - m) * inv * gs[d] + bts[d];
            xs[d * 32 + tid] = xv;
            g_x[row * Dm + d] = xv;
        }
    }
    __syncthreads();
    const float scale = rsqrtf(17.f);
    int lane = tid & 31, w = tid >> 5;
    int s = row0 + lane;
    for (int cc = w; cc < 102; cc += 8) {
        float acc = bs[cc];
        const float* wp = ws + cc * Dm;
#pragma unroll
        for (int d = 0; d < Dm; d++) acc = fmaf(xs[d * 32 + lane], wp[d], acc);
        if (s < S) {
            int kind = cc / Dm;
            int c2 = cc % Dm;
            int h = c2 / HD, dd = c2 % HD;
            int off = (h * S + s) * PH + dd;
            if (kind == 0)      g_q[off] = acc * scale;
            else if (kind == 1) g_k[off] = acc;
            else                g_v[off] = acc;
        }
    }
}

// ---------------------------------------------------------------------------
// K6 (fused agent tail, R11 form)
// ---------------------------------------------------------------------------
__global__ void __launch_bounds__(256) agent_tail(
    const float* __restrict__ opw2, const float* __restrict__ opb2,
    const float* __restrict__ g12,  const float* __restrict__ b12,
    const float* __restrict__ l1w2, const float* __restrict__ l1b2,
    const float* __restrict__ l2w2, const float* __restrict__ l2b2,
    const float* __restrict__ g22,  const float* __restrict__ b22,
    float* __restrict__ out)
{
    __shared__ __align__(16) float sm[4800];
    int tid = threadIdx.x;
    int b = blockIdx.x;
    unsigned ls = 0;

    {
        int h = b / NSEG2;
        int seg = b % NSEG2;
        int k0 = seg * KSEG2;
        int n = min(KSEG2, S - k0);
        float* Ks = sm;
        float* Vs = sm + 1800;
        const float4* ksrc = (const float4*)(g_k + (h * S + k0) * PH);
        const float4* vsrc = (const float4*)(g_v + (h * S + k0) * PH);
        float4* kdst = (float4*)Ks; float4* vdst = (float4*)Vs;
        for (int i = tid; i < n * 5; i += 256) { kdst[i] = ksrc[i]; vdst[i] = vsrc[i]; }
        __syncthreads();
        if (tid < HW) {
            int start = g_agent * HW;
            u64 q[9], acc[9];
            const u64* qp = (const u64*)(g_q + (h * S + start + tid) * PH);
#pragma unroll
            for (int i = 0; i < 9; i++) { q[i] = qp[i]; acc[i] = 0ULL; }
            float ssum = 0.f;
            const ulonglong2* K2 = (const ulonglong2*)Ks;
            const ulonglong2* V2 = (const ulonglong2*)Vs;
            for (int kk = 0; kk < n; kk++) {
                ulonglong2 ka = K2[0], kb = K2[1], kc = K2[2], kd = K2[3];
                u64 ke = K2[4].x;
                u64 t0 = mul2(q[0], ka.x),  t1 = mul2(q[1], ka.y);
                t0 = fma2(q[2], kb.x, t0);  t1 = fma2(q[3], kb.y, t1);
                t0 = fma2(q[4], kc.x, t0);  t1 = fma2(q[5], kc.y, t1);
                t0 = fma2(q[6], kd.x, t0);  t1 = fma2(q[7], kd.y, t1);
                t0 = fma2(q[8], ke, t0);
                t0 = add2(t0, t1);
                float2 f = unpk(t0);
                float p = __expf(f.x + f.y);
                ssum += p;
                u64 pp = pk(p, p);
                ulonglong2 va = V2[0], vb = V2[1], vc = V2[2], vd = V2[3];
                u64 ve = V2[4].x;
                acc[0] = fma2(pp, va.x, acc[0]); acc[1] = fma2(pp, va.y, acc[1]);
                acc[2] = fma2(pp, vb.x, acc[2]); acc[3] = fma2(pp, vb.y, acc[3]);
                acc[4] = fma2(pp, vc.x, acc[4]); acc[5] = fma2(pp, vc.y, acc[5]);
                acc[6] = fma2(pp, vd.x, acc[6]); acc[7] = fma2(pp, vd.y, acc[7]);
                acc[8] = fma2(pp, ve, acc[8]);
                K2 += 5; V2 += 5;
            }
            u64* pa = (u64*)(g_pacca + ((h * NSEG2 + seg) * HW + tid) * PAC);
#pragma unroll
            for (int i = 0; i < 9; i++) pa[i] = acc[i];
            g_psuma[(h * NSEG2 + seg) * HW + tid] = ssum;
        }
    }
    gsync(ls);  // 1

    {
        int e = b * 256 + tid;
        if (b < 11 && e < HW * Dm) {
            int r = e / Dm, c = e % Dm;
            int h = c / HD, d = c % HD;
            float a = 0.f, smm = 0.f;
#pragma unroll 4
            for (int g = 0; g < NSEG2; g++) {
                a   += g_pacca[((h * NSEG2 + g) * HW + r) * PAC + d];
                smm += g_psuma[(h * NSEG2 + g) * HW + r];
            }
            g_oa[e] = a / smm;
        }
    }
    gsync(ls);  // 2

    if (b == 0) {
        float* ws  = sm;
        float* bs  = sm + 1156;
        float* gs  = sm + 1190;
        float* bts = sm + 1224;
        for (int i = tid; i < Dm * Dm; i += 256) ws[i] = opw2[i];
        if (tid < Dm) { bs[tid] = opb2[tid]; gs[tid] = g12[tid]; bts[tid] = b12[tid]; }
        __syncthreads();
        if (tid < HW) {
            int s = g_agent * HW + tid;
            float orow[Dm], y[Dm];
#pragma unroll
            for (int d = 0; d < Dm; d++) orow[d] = g_oa[tid * Dm + d];
#pragma unroll 2
            for (int d = 0; d < Dm; d++) {
                float a = bs[d] + g_x[s * Dm + d];
                const float* wp = ws + d * Dm;
#pragma unroll
                for (int k = 0; k < Dm; k++) a = fmaf(orow[k], wp[k], a);
                y[d] = a;
            }
            float m = 0.f;
#pragma unroll
            for (int d = 0; d < Dm; d++) m += y[d];
            m *= (1.0f / Dm);
            float v = 0.f;
#pragma unroll
            for (int d = 0; d < Dm; d++) { float tt = y[d] - m; v = fmaf(tt, tt, v); }
            v *= (1.0f / Dm);
            float inv = rsqrtf(v + EPSV);
#pragma unroll
            for (int d = 0; d < Dm; d++) g_xa[tid * Dm + d] = (y[d] - m) * inv * gs[d] + bts[d];
        }
    }
    gsync(ls);  // 3

    if (b < NFSEG2) {
        float* W1s = sm;
        float* W2s = sm + 2304;
        float* b1s = sm + 4608;
        int fbase = b * FSEG2;
        for (int e = tid; e < FSEG2 * Dm; e += 256) {
            int f = e / Dm, d = e % Dm;
            W1s[f * 36 + d] = l1w2[(fbase + f) * Dm + d];
            W2s[f * 36 + d] = l2w2[d * FFd + fbase + f];
        }
        if (tid < FSEG2) b1s[tid] = l1b2[fbase + tid];
        __syncthreads();
        if (tid < HW) {
            u64 xr[17], y[17];
            const u64* p = (const u64*)(g_xa + tid * Dm);
#pragma unroll
            for (int i = 0; i < 17; i++) { xr[i] = p[i]; y[i] = 0ULL; }
#pragma unroll 2
            for (int f = 0; f < FSEG2; f++) {
                const ulonglong2* w2p = (const ulonglong2*)(W1s + f * 36);
                const u64*        w1p = (const u64*)(W1s + f * 36);
                ulonglong2 a0 = w2p[0], a1 = w2p[1], a2 = w2p[2], a3 = w2p[3];
                ulonglong2 a4 = w2p[4], a5 = w2p[5], a6 = w2p[6], a7 = w2p[7];
                u64 a16 = w1p[16];
                u64 t0 = mul2(xr[0], a0.x),  t1 = mul2(xr[1], a0.y);
                t0 = fma2(xr[2], a1.x, t0);  t1 = fma2(xr[3], a1.y, t1);
                t0 = fma2(xr[4], a2.x, t0);  t1 = fma2(xr[5], a2.y, t1);
                t0 = fma2(xr[6], a3.x, t0);  t1 = fma2(xr[7], a3.y, t1);
                t0 = fma2(xr[8], a4.x, t0);  t1 = fma2(xr[9], a4.y, t1);
                t0 = fma2(xr[10], a5.x, t0); t1 = fma2(xr[11], a5.y, t1);
                t0 = fma2(xr[12], a6.x, t0); t1 = fma2(xr[13], a6.y, t1);
                t0 = fma2(xr[14], a7.x, t0); t1 = fma2(xr[15], a7.y, t1);
                t0 = fma2(xr[16], a16, t0);
                t0 = add2(t0, t1);
                float2 fh = unpk(t0);
                float hrelu = fmaxf(fh.x + fh.y + b1s[f], 0.f);
                u64 hp = pk(hrelu, hrelu);
                const ulonglong2* v2p = (const ulonglong2*)(W2s + f * 36);
                const u64*        v1p = (const u64*)(W2s + f * 36);
                ulonglong2 b0 = v2p[0], b1v = v2p[1], b2v = v2p[2], b3 = v2p[3];
                ulonglong2 b4 = v2p[4], b5 = v2p[5], b6 = v2p[6], b7 = v2p[7];
                u64 b16 = v1p[16];
                y[0]  = fma2(hp, b0.x, y[0]);   y[1]  = fma2(hp, b0.y, y[1]);
                y[2]  = fma2(hp, b1v.x, y[2]);  y[3]  = fma2(hp, b1v.y, y[3]);
                y[4]  = fma2(hp, b2v.x, y[4]);  y[5]  = fma2(hp, b2v.y, y[5]);
                y[6]  = fma2(hp, b3.x, y[6]);   y[7]  = fma2(hp, b3.y, y[7]);
                y[8]  = fma2(hp, b4.x, y[8]);   y[9]  = fma2(hp, b4.y, y[9]);
                y[10] = fma2(hp, b5.x, y[10]);  y[11] = fma2(hp, b5.y, y[11]);
                y[12] = fma2(hp, b6.x, y[12]);  y[13] = fma2(hp, b6.y, y[13]);
                y[14] = fma2(hp, b7.x, y[14]);  y[15] = fma2(hp, b7.y, y[15]);
                y[16] = fma2(hp, b16, y[16]);
            }
            u64* yo = (u64*)(g_ypa + ((size_t)b * HW + tid) * Dm);
#pragma unroll
            for (int i = 0; i < 17; i++) yo[i] = y[i];
        }
    }
    gsync(ls);  // 4

    if (b == 0) {
        float* rows = sm;
        if (tid < HW) {
            float y[Dm];
#pragma unroll
            for (int d = 0; d < Dm; d++) y[d] = g_xa[tid * Dm + d] + l2b2[d];
            for (int g = 0; g < NFSEG2; g++) {
                const float* yp = g_ypa + ((size_t)g * HW + tid) * Dm;
#pragma unroll
                for (int d = 0; d < Dm; d++) y[d] += yp[d];
            }
            float m = 0.f;
#pragma unroll
            for (int d = 0; d < Dm; d++) m += y[d];
            m *= (1.0f / Dm);
            float v = 0.f;
#pragma unroll
            for (int d = 0; d < Dm; d++) { float tt = y[d] - m; v = fmaf(tt, tt, v); }
            v *= (1.0f / Dm);
            float inv = rsqrtf(v + EPSV);
#pragma unroll
            for (int d = 0; d < Dm; d++) rows[tid * Dm + d] = (y[d] - m) * inv * g22[d] + b22[d];
        }
        __syncthreads();
        if (tid < Dm) {
            float s = 0.f;
            for (int r = 0; r < HW; r++) s += rows[r * Dm + tid];
            out[tid] = s * (1.0f / 81.0f);
        }
    }
}

// ---------------------------------------------------------------------------
extern "C" void kernel_launch(void* const* d_in, const int* in_sizes, int n_in,
                              void* d_out, int out_size) {
    const float* obs = (const float*)d_in[0];
    const float* c1w = (const float*)d_in[1];
    const float* c1b = (const float*)d_in[2];
    const float* c2w = (const float*)d_in[3];
    const float* c2b = (const float*)d_in[4];
    const float* ipw = (const float*)d_in[5];
    const float* ipb = (const float*)d_in[6];
    const float* opw = (const float*)d_in[7];
    const float* opb = (const float*)d_in[8];
    const float* l1w = (const float*)d_in[9];
    const float* l1b = (const float*)d_in[10];
    const float* l2w = (const float*)d_in[11];
    const float* l2b = (const float*)d_in[12];
    const float* g1  = (const float*)d_in[13];
    const float* b1  = (const float*)d_in[14];
    const float* g2  = (const float*)d_in[15];
    const float* b2  = (const float*)d_in[16];
    float* out = (float*)d_out;

    front<<<148, 256>>>(obs, c1w, c1b, c2w, c2b, ipw, ipb);
    attn_struct<<<dim3(HW, NH), 512>>>();
    tokens_proj_ln<<<(S + 63) / 64, 128>>>(opw, opb, g1, b1);
    ffn0<<<dim3((S + 127) / 128, 1, NFSEG), 64>>>(l1w, l1b, l2w);
    ffnred_qkv<<<(S + 31) / 32, 256>>>(ipw + 102 * Dm, ipb + 102, l2b, g2, b2);
    agent_tail<<<148, 256>>>(opw + Dm * Dm, opb + Dm, g1 + Dm, b1 + Dm,
                             l1w + FFd * Dm, l1b + FFd, l2w + Dm * FFd, l2b + Dm,
                             g2 + Dm, b2 + Dm, out);
}

// round 15
// speedup vs baseline: 1.3095x; 1.0371x over previous
#include <cuda_runtime.h>

#define S      6561
#define Dm     34
#define HD     17
#define PH     20
#define PAC    18
#define FFd    2048
#define NH     2
#define HW     81
#define EPSV   1e-5f
#define ESTR   (NH * HW * HW)
// layer-0 FFN tiling: 16 f-segments of 128, 2 rows/thread, 128-thread blocks
#define NFSEG  16
#define FSEG   128
#define FCHK0  64
// layer-1 agent attention: 2 heads x 74 segs = 148 blocks
#define NSEG2  74
#define KSEG2  89
// agent FFN split
#define NFSEG2 32
#define FSEG2  64

typedef unsigned long long u64;

// ---- packed fp32 helpers ----
__device__ __forceinline__ u64 fma2(u64 a, u64 b, u64 c) {
    u64 d; asm("fma.rn.f32x2 %0, %1, %2, %3;" : "=l"(d) : "l"(a), "l"(b), "l"(c)); return d;
}
__device__ __forceinline__ u64 mul2(u64 a, u64 b) {
    u64 d; asm("mul.rn.f32x2 %0, %1, %2;" : "=l"(d) : "l"(a), "l"(b)); return d;
}
__device__ __forceinline__ u64 add2(u64 a, u64 b) {
    u64 d; asm("add.rn.f32x2 %0, %1, %2;" : "=l"(d) : "l"(a), "l"(b)); return d;
}
__device__ __forceinline__ float2 unpk(u64 v) {
    float2 f; asm("mov.b64 {%0, %1}, %2;" : "=f"(f.x), "=f"(f.y) : "l"(v)); return f;
}
__device__ __forceinline__ u64 pk(float x, float y) {
    u64 v; asm("mov.b64 %0, {%1, %2};" : "=l"(v) : "f"(x), "f"(y)); return v;
}

// ---- device-global scratch ----
__device__ unsigned g_cnt;
__device__ unsigned g_sense;
__device__ int   g_agent;
__device__ __align__(16) float g_emb[HW * 16];
__device__ __align__(16) float g_x[S * Dm];
__device__ __align__(16) float g_q[NH * S * PH];
__device__ __align__(16) float g_k[NH * S * PH];
__device__ __align__(16) float g_v[NH * S * PH];
__device__ __align__(16) float g_o[S * Dm];
__device__ __align__(16) float g_yp[NFSEG * S * Dm];
__device__ __align__(16) float g_QA[NH * HW * HD];
__device__ __align__(16) float g_QB[NH * HW * HD];
__device__ __align__(16) float g_KA[NH * HW * HD];
__device__ __align__(16) float g_KB[NH * HW * HD];
__device__ __align__(16) float g_VA[NH * HW * HD];
__device__ __align__(16) float g_VB[NH * HW * HD];
__device__ __align__(16) float g_E[4 * ESTR];    // EA, EB row-major; EC, ED TRANSPOSED
__device__ __align__(16) float g_pacca[NH * NSEG2 * HW * PAC];
__device__ float g_psuma[NH * NSEG2 * HW];
__device__ __align__(16) float g_xa[HW * Dm];
__device__ __align__(16) float g_ypa[NFSEG2 * HW * Dm];
__device__ __align__(16) float g_oa[HW * Dm];

// ---- sense-reversing grid barrier (all blocks resident) ----
__device__ __forceinline__ void gsync(unsigned& ls) {
    __syncthreads();
    if (threadIdx.x == 0) {
        unsigned ns = ls ^ 1u;
        __threadfence();
        unsigned old = atomicAdd(&g_cnt, 1u);
        if (old == gridDim.x - 1u) {
            g_cnt = 0u;
            __threadfence();
            atomicExch(&g_sense, ns);
        } else {
            while (atomicAdd(&g_sense, 0u) != ns) { __nanosleep(64); }
        }
        ls = ns;
        __threadfence();
    }
    __syncthreads();
}

// ---------------------------------------------------------------------------
// K1 (fused front): conv+argmax -> basis QKV -> exp(logits). grid 148x256.
// ---------------------------------------------------------------------------
__global__ void __launch_bounds__(256) front(
    const float* __restrict__ obs,
    const float* __restrict__ c1w, const float* __restrict__ c1b,
    const float* __restrict__ c2w, const float* __restrict__ c2b,
    const float* __restrict__ ipw, const float* __restrict__ ipb)
{
    __shared__ float so[192];
    __shared__ float c1s[1296];
    int tid = threadIdx.x;
    int b = blockIdx.x;
    unsigned ls = 0;

    if (b == 0) {
        for (int i = tid; i < 162; i += 256) so[i] = obs[i];
        __syncthreads();
        if (tid == 0) {
            float mx = so[0]; int mi = 0;
            for (int i = 1; i < 81; i++) if (so[i] > mx) { mx = so[i]; mi = i; }
            g_agent = mi;
        }
        for (int idx = tid; idx < 16 * 81; idx += 256) {
            int ch = idx / 81, pos = idx % 81, r = pos / 9, c = pos % 9;
            float acc = c1b[ch];
            for (int ci = 0; ci < 2; ci++)
                for (int dr = 0; dr < 3; dr++) {
                    int rr = r + dr - 1; if (rr < 0 || rr >= 9) continue;
                    for (int dc = 0; dc < 3; dc++) {
                        int cc = c + dc - 1; if (cc < 0 || cc >= 9) continue;
                        acc += so[ci * 81 + rr * 9 + cc] * c1w[((ch * 2 + ci) * 3 + dr) * 3 + dc];
                    }
                }
            c1s[idx] = fmaxf(acc, 0.f);
        }
        __syncthreads();
        for (int idx = tid; idx < 16 * 81; idx += 256) {
            int ch = idx / 81, pos = idx % 81, r = pos / 9, c = pos % 9;
            float acc = c2b[ch];
            for (int ci = 0; ci < 16; ci++)
                for (int dr = 0; dr < 3; dr++) {
                    int rr = r + dr - 1; if (rr < 0 || rr >= 9) continue;
                    for (int dc = 0; dc < 3; dc++) {
                        int cc = c + dc - 1; if (cc < 0 || cc >= 9) continue;
                        acc += c1s[ci * 81 + rr * 9 + cc] * c2w[((ch * 16 + ci) * 3 + dr) * 3 + dc];
                    }
                }
            g_emb[pos * 16 + ch] = fmaxf(acc, 0.f);
        }
    }
    gsync(ls);  // 1

    for (int idx = b * 256 + tid; idx < 162 * 102; idx += 148 * 256) {
        int v = idx / 102, c = idx % 102;
        const float* wr = ipw + c * Dm;
        float acc;
        if (v < 81) {
            int i = v;
            acc = ipb[c];
#pragma unroll
            for (int d = 0; d < 16; d++) acc = fmaf(g_emb[i * 16 + d], wr[d], acc);
            acc = fmaf((float)(i / 9) * 0.25f, wr[32], acc);
            acc = fmaf((float)(i % 9) * 0.25f, wr[33], acc);
        } else {
            int j = v - 81;
            acc = 0.f;
#pragma unroll
            for (int d = 0; d < 16; d++) acc = fmaf(g_emb[j * 16 + d], wr[16 + d], acc);
            acc = fmaf(-(float)(j / 9) * 0.25f, wr[32], acc);
            acc = fmaf(-(float)(j % 9) * 0.25f, wr[33], acc);
        }
        int kind = c / Dm;
        int cc = c % Dm;
        int h = cc / HD, dd = cc % HD;
        int off = (h * HW + (v % 81)) * HD + dd;
        if (kind == 0) {
            float sv = acc * rsqrtf(17.f);
            if (v < 81) g_QA[off] = sv; else g_QB[off] = sv;
        } else if (kind == 1) {
            if (v < 81) g_KA[off] = acc; else g_KB[off] = acc;
        } else {
            if (v < 81) g_VA[off] = acc; else g_VB[off] = acc;
        }
    }
    gsync(ls);  // 2

    for (int idx = b * 256 + tid; idx < 4 * ESTR; idx += 148 * 256) {
        int p = idx / ESTR;
        int r = idx % ESTR;
        int h = r / (HW * HW);
        int q2 = r % (HW * HW);
        int i = q2 / HW, m = q2 % HW;
        const float* L;
        const float* R;
        if (p == 0)      { L = g_QA + (h * HW + i) * HD; R = g_KA + (h * HW + m) * HD; }
        else if (p == 1) { L = g_QA + (h * HW + i) * HD; R = g_KB + (h * HW + m) * HD; }
        else if (p == 2) { L = g_KA + (h * HW + i) * HD; R = g_QB + (h * HW + m) * HD; }
        else             { L = g_KB + (h * HW + i) * HD; R = g_QB + (h * HW + m) * HD; }
        float dot = 0.f;
#pragma unroll
        for (int d = 0; d < HD; d++) dot = fmaf(L[d], R[d], dot);
        g_E[idx] = __expf(dot);
    }
}

// ---------------------------------------------------------------------------
// K2 (fused): structured attention (both heads) + tokens + out_proj + LN1.
// grid 81 x 512. Block i produces g_o rows [i*81, i*81+81) then consumes them.
// ---------------------------------------------------------------------------
__global__ void __launch_bounds__(512) attn_tok(const float* __restrict__ opw,
                                                const float* __restrict__ opb,
                                                const float* __restrict__ gg,
                                                const float* __restrict__ bb) {
    __shared__ __align__(16) float sm[12180];   // 48720 B
    int tid = threadIdx.x;
    int i = blockIdx.x;

    // ---- attention phase (per head) ----
    {
        float* sea  = sm;                  // 96
        float* seb  = sm + 96;             // 96
        float* sva  = sm + 192;            // 2916
        float* svb  = sm + 3108;           // 2916
        float* psum = sm + 6024;           // 324
        u64*   pacc = (u64*)(sm + 6348);   // 2916 u64 (5832 floats) -> 12180
        for (int h = 0; h < NH; h++) {
            __syncthreads();
            for (int t = tid; t < HW; t += 512) {
                sea[t] = g_E[0 * ESTR + (h * HW + i) * HW + t];
                seb[t] = g_E[1 * ESTR + (h * HW + i) * HW + t];
            }
            for (int t = tid; t < HW * 18; t += 512) {
                int m = t / 18, d = t % 18;
                sva[t] = (d < HD) ? g_VA[(h * HW + m) * HD + d] : 0.f;
                svb[t] = (d < HD) ? g_VB[(h * HW + m) * HD + d] : 0.f;
            }
            __syncthreads();
            int quad = tid >> 7;
            int j = tid & 127;
            if (j < HW) {
                bool isA = quad < 2;
                int lo = (quad & 1) ? 41 : 0;
                int hi = (quad & 1) ? HW : 41;
                const float* et = g_E + (isA ? 2 : 3) * ESTR + h * HW * HW + j;
                const float* se = isA ? sea : seb;
                const float* sv = isA ? sva : svb;
                float z = 0.f;
                u64 w[9];
#pragma unroll
                for (int k = 0; k < 9; k++) w[k] = 0ULL;
#pragma unroll 4
                for (int m = lo; m < hi; m++) {
                    float f = se[m] * et[m * HW];
                    z += f;
                    u64 fp = pk(f, f);
                    const u64* vr = (const u64*)(sv + m * 18);
#pragma unroll
                    for (int k = 0; k < 9; k++) w[k] = fma2(fp, vr[k], w[k]);
                }
                psum[quad * HW + j] = z;
                u64* pw = pacc + (quad * HW + j) * 9;
#pragma unroll
                for (int k = 0; k < 9; k++) pw[k] = w[k];
            }
            __syncthreads();
            if (tid < HW) {
                int jj = tid;
                float zm = psum[jj] + psum[HW + jj];
                float zn = psum[2 * HW + jj] + psum[3 * HW + jj];
                const u64* p0 = pacc + jj * 9;
                const u64* p1 = pacc + (HW + jj) * 9;
                const u64* p2 = pacc + (2 * HW + jj) * 9;
                const u64* p3 = pacc + (3 * HW + jj) * 9;
                float inv = 1.0f / (zm * zn);
                float* od = g_o + (i * HW + jj) * Dm + h * HD;
#pragma unroll
                for (int k = 0; k < 9; k++) {
                    float2 A = unpk(add2(p0[k], p1[k]));
                    float2 B = unpk(add2(p2[k], p3[k]));
                    int d = 2 * k;
                    od[d] = (A.x * zn + B.x * zm) * inv;
                    if (d + 1 < HD) od[d + 1] = (A.y * zn + B.y * zm) * inv;
                }
            }
        }
    }
    __syncthreads();

    // ---- token phase: tokens + out_proj + residual + LN1 (rows of this block) ----
    {
        float* embs = sm;            // 1296
        float* ws   = sm + 1296;     // 1156
        float* bs   = sm + 2452;     // 34
        float* gs   = sm + 2486;     // 34
        float* bts  = sm + 2520;     // 34
        float* ys   = sm + 2560;     // 81*36 = 2916
        for (int e = tid; e < 1296; e += 512) embs[e] = g_emb[e];
        for (int e = tid; e < Dm * Dm; e += 512) ws[e] = opw[e];
        if (tid < Dm) { bs[tid] = opb[tid]; gs[tid] = gg[tid]; bts[tid] = bb[tid]; }
        __syncthreads();
        int q = tid >> 7;
        int j = tid & 127;
        int t = i * HW + j;
        if (j < HW) {
            int jj = t % HW;     // == j
            float orow[Dm];
#pragma unroll
            for (int d = 0; d < Dm; d++) orow[d] = g_o[t * Dm + d];
            int dlo = q * 9;
            int dhi = min(Dm, dlo + 9);
#pragma unroll 1
            for (int d = dlo; d < dhi; d++) {
                float xv;
                if (d < 16)       xv = embs[i * 16 + d];
                else if (d < 32)  xv = embs[jj * 16 + (d - 16)];
                else if (d == 32) xv = ((float)(i / 9) - (float)(jj / 9)) * 0.25f;
                else              xv = ((float)(i % 9) - (float)(jj % 9)) * 0.25f;
                float a = bs[d] + xv;
                const float* wp = ws + d * Dm;
#pragma unroll
                for (int k = 0; k < Dm; k++) a = fmaf(orow[k], wp[k], a);
                ys[j * 36 + d] = a;
            }
        }
        __syncthreads();
        if (q == 0 && j < HW) {
            float y[Dm];
#pragma unroll
            for (int d = 0; d < Dm; d++) y[d] = ys[j * 36 + d];
            float m = 0.f;
#pragma unroll
            for (int d = 0; d < Dm; d++) m += y[d];
            m *= (1.0f / Dm);
            float v = 0.f;
#pragma unroll
            for (int d = 0; d < Dm; d++) { float tt = y[d] - m; v = fmaf(tt, tt, v); }
            v *= (1.0f / Dm);
            float inv = rsqrtf(v + EPSV);
#pragma unroll
            for (int d = 0; d < Dm; d++) g_x[t * Dm + d] = (y[d] - m) * inv * gs[d] + bts[d];
        }
    }
}

// ---------------------------------------------------------------------------
// K3: layer-0 FFN partials — 2 rows/thread, 128-thread blocks, 3 blocks/SM
// (444 slots >= 416 blocks -> single wave). grid (26, 1, 16).
// ---------------------------------------------------------------------------
__global__ void __launch_bounds__(128, 3) ffn0(const float* __restrict__ l1w,
                                               const float* __restrict__ l1b,
                                               const float* __restrict__ l2w) {
    __shared__ __align__(16) float W1s[FCHK0 * 36];
    __shared__ __align__(16) float W2s[FCHK0 * 36];
    __shared__ float b1s[FCHK0];
    int tid = threadIdx.x;
    int row0 = blockIdx.x * 256 + tid;
    int row1 = row0 + 128;
    int fbase = blockIdx.z * FSEG;
    bool a0 = row0 < S, a1 = row1 < S;
    u64 x0[17], x1[17], y0[17], y1[17];
#pragma unroll
    for (int i = 0; i < 17; i++) { x0[i] = 0ULL; x1[i] = 0ULL; y0[i] = 0ULL; y1[i] = 0ULL; }
    if (a0) {
        const u64* p = (const u64*)(g_x + row0 * Dm);
#pragma unroll
        for (int i = 0; i < 17; i++) x0[i] = p[i];
    }
    if (a1) {
        const u64* p = (const u64*)(g_x + row1 * Dm);
#pragma unroll
        for (int i = 0; i < 17; i++) x1[i] = p[i];
    }
    for (int fc = fbase; fc < fbase + FSEG; fc += FCHK0) {
        for (int e = tid; e < FCHK0 * Dm; e += 128) {
            int f = e / Dm, d = e % Dm;
            W1s[f * 36 + d] = l1w[(fc + f) * Dm + d];
            W2s[f * 36 + d] = l2w[d * FFd + fc + f];
        }
        if (tid < FCHK0) b1s[tid] = l1b[fc + tid];
        __syncthreads();
#pragma unroll 2
        for (int f = 0; f < FCHK0; f++) {
            const ulonglong2* w2p = (const ulonglong2*)(W1s + f * 36);
            const u64*        w1p = (const u64*)(W1s + f * 36);
            ulonglong2 a0v = w2p[0], a1v = w2p[1], a2v = w2p[2], a3v = w2p[3];
            ulonglong2 a4v = w2p[4], a5v = w2p[5], a6v = w2p[6], a7v = w2p[7];
            u64 a16 = w1p[16];
            u64 t0 = mul2(x0[0], a0v.x),  t1 = mul2(x0[1], a0v.y);
            u64 u0 = mul2(x1[0], a0v.x),  u1 = mul2(x1[1], a0v.y);
            t0 = fma2(x0[2], a1v.x, t0);  t1 = fma2(x0[3], a1v.y, t1);
            u0 = fma2(x1[2], a1v.x, u0);  u1 = fma2(x1[3], a1v.y, u1);
            t0 = fma2(x0[4], a2v.x, t0);  t1 = fma2(x0[5], a2v.y, t1);
            u0 = fma2(x1[4], a2v.x, u0);  u1 = fma2(x1[5], a2v.y, u1);
            t0 = fma2(x0[6], a3v.x, t0);  t1 = fma2(x0[7], a3v.y, t1);
            u0 = fma2(x1[6], a3v.x, u0);  u1 = fma2(x1[7], a3v.y, u1);
            t0 = fma2(x0[8], a4v.x, t0);  t1 = fma2(x0[9], a4v.y, t1);
            u0 = fma2(x1[8], a4v.x, u0);  u1 = fma2(x1[9], a4v.y, u1);
            t0 = fma2(x0[10], a5v.x, t0); t1 = fma2(x0[11], a5v.y, t1);
            u0 = fma2(x1[10], a5v.x, u0); u1 = fma2(x1[11], a5v.y, u1);
            t0 = fma2(x0[12], a6v.x, t0); t1 = fma2(x0[13], a6v.y, t1);
            u0 = fma2(x1[12], a6v.x, u0); u1 = fma2(x1[13], a6v.y, u1);
            t0 = fma2(x0[14], a7v.x, t0); t1 = fma2(x0[15], a7v.y, t1);
            u0 = fma2(x1[14], a7v.x, u0); u1 = fma2(x1[15], a7v.y, u1);
            t0 = fma2(x0[16], a16, t0);
            u0 = fma2(x1[16], a16, u0);
            t0 = add2(t0, t1);
            u0 = add2(u0, u1);
            float2 fh0 = unpk(t0), fh1 = unpk(u0);
            float h0 = fmaxf(fh0.x + fh0.y + b1s[f], 0.f);
            float h1 = fmaxf(fh1.x + fh1.y + b1s[f], 0.f);
            u64 hp0 = pk(h0, h0), hp1 = pk(h1, h1);
            const ulonglong2* v2p = (const ulonglong2*)(W2s + f * 36);
            const u64*        v1p = (const u64*)(W2s + f * 36);
            ulonglong2 b0v = v2p[0], b1v = v2p[1], b2v = v2p[2], b3v = v2p[3];
            ulonglong2 b4v = v2p[4], b5v = v2p[5], b6v = v2p[6], b7v = v2p[7];
            u64 b16 = v1p[16];
            y0[0]  = fma2(hp0, b0v.x, y0[0]);   y1[0]  = fma2(hp1, b0v.x, y1[0]);
            y0[1]  = fma2(hp0, b0v.y, y0[1]);   y1[1]  = fma2(hp1, b0v.y, y1[1]);
            y0[2]  = fma2(hp0, b1v.x, y0[2]);   y1[2]  = fma2(hp1, b1v.x, y1[2]);
            y0[3]  = fma2(hp0, b1v.y, y0[3]);   y1[3]  = fma2(hp1, b1v.y, y1[3]);
            y0[4]  = fma2(hp0, b2v.x, y0[4]);   y1[4]  = fma2(hp1, b2v.x, y1[4]);
            y0[5]  = fma2(hp0, b2v.y, y0[5]);   y1[5]  = fma2(hp1, b2v.y, y1[5]);
            y0[6]  = fma2(hp0, b3v.x, y0[6]);   y1[6]  = fma2(hp1, b3v.x, y1[6]);
            y0[7]  = fma2(hp0, b3v.y, y0[7]);   y1[7]  = fma2(hp1, b3v.y, y1[7]);
            y0[8]  = fma2(hp0, b4v.x, y0[8]);   y1[8]  = fma2(hp1, b4v.x, y1[8]);
            y0[9]  = fma2(hp0, b4v.y, y0[9]);   y1[9]  = fma2(hp1, b4v.y, y1[9]);
            y0[10] = fma2(hp0, b5v.x, y0[10]);  y1[10] = fma2(hp1, b5v.x, y1[10]);
            y0[11] = fma2(hp0, b5v.y, y0[11]);  y1[11] = fma2(hp1, b5v.y, y1[11]);
            y0[12] = fma2(hp0, b6v.x, y0[12]);  y1[12] = fma2(hp1, b6v.x, y1[12]);
            y0[13] = fma2(hp0, b6v.y, y0[13]);  y1[13] = fma2(hp1, b6v.y, y1[13]);
            y0[14] = fma2(hp0, b7v.x, y0[14]);  y1[14] = fma2(hp1, b7v.x, y1[14]);
            y0[15] = fma2(hp0, b7v.y, y0[15]);  y1[15] = fma2(hp1, b7v.y, y1[15]);
            y0[16] = fma2(hp0, b16, y0[16]);    y1[16] = fma2(hp1, b16, y1[16]);
        }
        __syncthreads();
    }
    if (a0) {
        u64* yo = (u64*)(g_yp + ((size_t)blockIdx.z * S + row0) * Dm);
#pragma unroll
        for (int i = 0; i < 17; i++) yo[i] = y0[i];
    }
    if (a1) {
        u64* yo = (u64*)(g_yp + ((size_t)blockIdx.z * S + row1) * Dm);
#pragma unroll
        for (int i = 0; i < 17; i++) yo[i] = y1[i];
    }
}

// ---------------------------------------------------------------------------
// K4: FFN reduce + LN2 + layer-1 QKV fused
// ---------------------------------------------------------------------------
__global__ void __launch_bounds__(256) ffnred_qkv(const float* __restrict__ ipw2,
                                                  const float* __restrict__ ipb2,
                                                  const float* __restrict__ l2b,
                                                  const float* __restrict__ gg,
                                                  const float* __restrict__ bb) {
    __shared__ float xs[Dm * 32];
    __shared__ float ws[102 * Dm];
    __shared__ float bs[102];
    __shared__ __align__(16) float pre[32 * 36];
    __shared__ float l2bs[Dm], gs[Dm], bts[Dm];
    int tid = threadIdx.x;
    int row0 = blockIdx.x * 32;
    for (int i = tid; i < 102 * Dm; i += 256) ws[i] = ipw2[i];
    if (tid < 102) bs[tid] = ipb2[tid];
    if (tid < Dm) { l2bs[tid] = l2b[tid]; gs[tid] = gg[tid]; bts[tid] = bb[tid]; }
    for (int e = tid; e < 32 * 17; e += 256) {
        int r = e / 17, k = e % 17;
        int row = row0 + r;
        if (row < S) {
            u64 acc = ((const u64*)(g_x + row * Dm))[k];
#pragma unroll
            for (int g = 0; g < NFSEG; g++)
                acc = add2(acc, ((const u64*)(g_yp + ((size_t)g * S + row) * Dm))[k]);
            ((u64*)(pre + r * 36))[k] = acc;
        }
    }
    __syncthreads();
    if (tid < 32 && row0 + tid < S) {
        float y[Dm];
#pragma unroll
        for (int d = 0; d < Dm; d++) y[d] = pre[tid * 36 + d] + l2bs[d];
        float m = 0.f;
#pragma unroll
        for (int d = 0; d < Dm; d++) m += y[d];
        m *= (1.0f / Dm);
        float v = 0.f;
#pragma unroll
        for (int d = 0; d < Dm; d++) { float tt = y[d] - m; v = fmaf(tt, tt, v); }
        v *= (1.0f / Dm);
        float inv = rsqrtf(v + EPSV);
        int row = row0 + tid;
#pragma unroll
        for (int d = 0; d < Dm; d++) {
            float xv = (y[d] - m) * inv * gs[d] + bts[d];
            xs[d * 32 + tid] = xv;
            g_x[row * Dm + d] = xv;
        }
    }
    __syncthreads();
    const float scale = rsqrtf(17.f);
    int lane = tid & 31, w = tid >> 5;
    int s = row0 + lane;
    for (int cc = w; cc < 102; cc += 8) {
        float acc = bs[cc];
        const float* wp = ws + cc * Dm;
#pragma unroll
        for (int d = 0; d < Dm; d++) acc = fmaf(xs[d * 32 + lane], wp[d], acc);
        if (s < S) {
            int kind = cc / Dm;
            int c2 = cc % Dm;
            int h = c2 / HD, dd = c2 % HD;
            int off = (h * S + s) * PH + dd;
            if (kind == 0)      g_q[off] = acc * scale;
            else if (kind == 1) g_k[off] = acc;
            else                g_v[off] = acc;
        }
    }
}

// ---------------------------------------------------------------------------
// K5 (fused agent tail)
// ---------------------------------------------------------------------------
__global__ void __launch_bounds__(256) agent_tail(
    const float* __restrict__ opw2, const float* __restrict__ opb2,
    const float* __restrict__ g12,  const float* __restrict__ b12,
    const float* __restrict__ l1w2, const float* __restrict__ l1b2,
    const float* __restrict__ l2w2, const float* __restrict__ l2b2,
    const float* __restrict__ g22,  const float* __restrict__ b22,
    float* __restrict__ out)
{
    __shared__ __align__(16) float sm[4800];
    int tid = threadIdx.x;
    int b = blockIdx.x;
    unsigned ls = 0;

    {
        int h = b / NSEG2;
        int seg = b % NSEG2;
        int k0 = seg * KSEG2;
        int n = min(KSEG2, S - k0);
        float* Ks = sm;
        float* Vs = sm + 1800;
        const float4* ksrc = (const float4*)(g_k + (h * S + k0) * PH);
        const float4* vsrc = (const float4*)(g_v + (h * S + k0) * PH);
        float4* kdst = (float4*)Ks; float4* vdst = (float4*)Vs;
        for (int i = tid; i < n * 5; i += 256) { kdst[i] = ksrc[i]; vdst[i] = vsrc[i]; }
        __syncthreads();
        if (tid < HW) {
            int start = g_agent * HW;
            u64 q[9], acc[9];
            const u64* qp = (const u64*)(g_q + (h * S + start + tid) * PH);
#pragma unroll
            for (int i = 0; i < 9; i++) { q[i] = qp[i]; acc[i] = 0ULL; }
            float ssum = 0.f;
            const ulonglong2* K2 = (const ulonglong2*)Ks;
            const ulonglong2* V2 = (const ulonglong2*)Vs;
            for (int kk = 0; kk < n; kk++) {
                ulonglong2 ka = K2[0], kb = K2[1], kc = K2[2], kd = K2[3];
                u64 ke = K2[4].x;
                u64 t0 = mul2(q[0], ka.x),  t1 = mul2(q[1], ka.y);
                t0 = fma2(q[2], kb.x, t0);  t1 = fma2(q[3], kb.y, t1);
                t0 = fma2(q[4], kc.x, t0);  t1 = fma2(q[5], kc.y, t1);
                t0 = fma2(q[6], kd.x, t0);  t1 = fma2(q[7], kd.y, t1);
                t0 = fma2(q[8], ke, t0);
                t0 = add2(t0, t1);
                float2 f = unpk(t0);
                float p = __expf(f.x + f.y);
                ssum += p;
                u64 pp = pk(p, p);
                ulonglong2 va = V2[0], vb = V2[1], vc = V2[2], vd = V2[3];
                u64 ve = V2[4].x;
                acc[0] = fma2(pp, va.x, acc[0]); acc[1] = fma2(pp, va.y, acc[1]);
                acc[2] = fma2(pp, vb.x, acc[2]); acc[3] = fma2(pp, vb.y, acc[3]);
                acc[4] = fma2(pp, vc.x, acc[4]); acc[5] = fma2(pp, vc.y, acc[5]);
                acc[6] = fma2(pp, vd.x, acc[6]); acc[7] = fma2(pp, vd.y, acc[7]);
                acc[8] = fma2(pp, ve, acc[8]);
                K2 += 5; V2 += 5;
            }
            u64* pa = (u64*)(g_pacca + ((h * NSEG2 + seg) * HW + tid) * PAC);
#pragma unroll
            for (int i = 0; i < 9; i++) pa[i] = acc[i];
            g_psuma[(h * NSEG2 + seg) * HW + tid] = ssum;
        }
    }
    gsync(ls);  // 1

    {
        int e = b * 256 + tid;
        if (b < 11 && e < HW * Dm) {
            int r = e / Dm, c = e % Dm;
            int h = c / HD, d = c % HD;
            float a = 0.f, smm = 0.f;
#pragma unroll 4
            for (int g = 0; g < NSEG2; g++) {
                a   += g_pacca[((h * NSEG2 + g) * HW + r) * PAC + d];
                smm += g_psuma[(h * NSEG2 + g) * HW + r];
            }
            g_oa[e] = a / smm;
        }
    }
    gsync(ls);  // 2

    if (b == 0) {
        float* ws  = sm;
        float* bs  = sm + 1156;
        float* gs  = sm + 1190;
        float* bts = sm + 1224;
        for (int i = tid; i < Dm * Dm; i += 256) ws[i] = opw2[i];
        if (tid < Dm) { bs[tid] = opb2[tid]; gs[tid] = g12[tid]; bts[tid] = b12[tid]; }
        __syncthreads();
        if (tid < HW) {
            int s = g_agent * HW + tid;
            float orow[Dm], y[Dm];
#pragma unroll
            for (int d = 0; d < Dm; d++) orow[d] = g_oa[tid * Dm + d];
#pragma unroll 2
            for (int d = 0; d < Dm; d++) {
                float a = bs[d] + g_x[s * Dm + d];
                const float* wp = ws + d * Dm;
#pragma unroll
                for (int k = 0; k < Dm; k++) a = fmaf(orow[k], wp[k], a);
                y[d] = a;
            }
            float m = 0.f;
#pragma unroll
            for (int d = 0; d < Dm; d++) m += y[d];
            m *= (1.0f / Dm);
            float v = 0.f;
#pragma unroll
            for (int d = 0; d < Dm; d++) { float tt = y[d] - m; v = fmaf(tt, tt, v); }
            v *= (1.0f / Dm);
            float inv = rsqrtf(v + EPSV);
#pragma unroll
            for (int d = 0; d < Dm; d++) g_xa[tid * Dm + d] = (y[d] - m) * inv * gs[d] + bts[d];
        }
    }
    gsync(ls);  // 3

    if (b < NFSEG2) {
        float* W1s = sm;
        float* W2s = sm + 2304;
        float* b1s = sm + 4608;
        int fbase = b * FSEG2;
        for (int e = tid; e < FSEG2 * Dm; e += 256) {
            int f = e / Dm, d = e % Dm;
            W1s[f * 36 + d] = l1w2[(fbase + f) * Dm + d];
            W2s[f * 36 + d] = l2w2[d * FFd + fbase + f];
        }
        if (tid < FSEG2) b1s[tid] = l1b2[fbase + tid];
        __syncthreads();
        if (tid < HW) {
            u64 xr[17], y[17];
            const u64* p = (const u64*)(g_xa + tid * Dm);
#pragma unroll
            for (int i = 0; i < 17; i++) { xr[i] = p[i]; y[i] = 0ULL; }
#pragma unroll 2
            for (int f = 0; f < FSEG2; f++) {
                const ulonglong2* w2p = (const ulonglong2*)(W1s + f * 36);
                const u64*        w1p = (const u64*)(W1s + f * 36);
                ulonglong2 a0 = w2p[0], a1 = w2p[1], a2 = w2p[2], a3 = w2p[3];
                ulonglong2 a4 = w2p[4], a5 = w2p[5], a6 = w2p[6], a7 = w2p[7];
                u64 a16 = w1p[16];
                u64 t0 = mul2(xr[0], a0.x),  t1 = mul2(xr[1], a0.y);
                t0 = fma2(xr[2], a1.x, t0);  t1 = fma2(xr[3], a1.y, t1);
                t0 = fma2(xr[4], a2.x, t0);  t1 = fma2(xr[5], a2.y, t1);
                t0 = fma2(xr[6], a3.x, t0);  t1 = fma2(xr[7], a3.y, t1);
                t0 = fma2(xr[8], a4.x, t0);  t1 = fma2(xr[9], a4.y, t1);
                t0 = fma2(xr[10], a5.x, t0); t1 = fma2(xr[11], a5.y, t1);
                t0 = fma2(xr[12], a6.x, t0); t1 = fma2(xr[13], a6.y, t1);
                t0 = fma2(xr[14], a7.x, t0); t1 = fma2(xr[15], a7.y, t1);
                t0 = fma2(xr[16], a16, t0);
                t0 = add2(t0, t1);
                float2 fh = unpk(t0);
                float hrelu = fmaxf(fh.x + fh.y + b1s[f], 0.f);
                u64 hp = pk(hrelu, hrelu);
                const ulonglong2* v2p = (const ulonglong2*)(W2s + f * 36);
                const u64*        v1p = (const u64*)(W2s + f * 36);
                ulonglong2 b0 = v2p[0], b1v = v2p[1], b2v = v2p[2], b3 = v2p[3];
                ulonglong2 b4 = v2p[4], b5 = v2p[5], b6 = v2p[6], b7 = v2p[7];
                u64 b16 = v1p[16];
                y[0]  = fma2(hp, b0.x, y[0]);   y[1]  = fma2(hp, b0.y, y[1]);
                y[2]  = fma2(hp, b1v.x, y[2]);  y[3]  = fma2(hp, b1v.y, y[3]);
                y[4]  = fma2(hp, b2v.x, y[4]);  y[5]  = fma2(hp, b2v.y, y[5]);
                y[6]  = fma2(hp, b3.x, y[6]);   y[7]  = fma2(hp, b3.y, y[7]);
                y[8]  = fma2(hp, b4.x, y[8]);   y[9]  = fma2(hp, b4.y, y[9]);
                y[10] = fma2(hp, b5.x, y[10]);  y[11] = fma2(hp, b5.y, y[11]);
                y[12] = fma2(hp, b6.x, y[12]);  y[13] = fma2(hp, b6.y, y[13]);
                y[14] = fma2(hp, b7.x, y[14]);  y[15] = fma2(hp, b7.y, y[15]);
                y[16] = fma2(hp, b16, y[16]);
            }
            u64* yo = (u64*)(g_ypa + ((size_t)b * HW + tid) * Dm);
#pragma unroll
            for (int i = 0; i < 17; i++) yo[i] = y[i];
        }
    }
    gsync(ls);  // 4

    if (b == 0) {
        float* rows = sm;
        if (tid < HW) {
            float y[Dm];
#pragma unroll
            for (int d = 0; d < Dm; d++) y[d] = g_xa[tid * Dm + d] + l2b2[d];
            for (int g = 0; g < NFSEG2; g++) {
                const float* yp = g_ypa + ((size_t)g * HW + tid) * Dm;
#pragma unroll
                for (int d = 0; d < Dm; d++) y[d] += yp[d];
            }
            float m = 0.f;
#pragma unroll
            for (int d = 0; d < Dm; d++) m += y[d];
            m *= (1.0f / Dm);
            float v = 0.f;
#pragma unroll
            for (int d = 0; d < Dm; d++) { float tt = y[d] - m; v = fmaf(tt, tt, v); }
            v *= (1.0f / Dm);
            float inv = rsqrtf(v + EPSV);
#pragma unroll
            for (int d = 0; d < Dm; d++) rows[tid * Dm + d] = (y[d] - m) * inv * g22[d] + b22[d];
        }
        __syncthreads();
        if (tid < Dm) {
            float s = 0.f;
            for (int r = 0; r < HW; r++) s += rows[r * Dm + tid];
            out[tid] = s * (1.0f / 81.0f);
        }
    }
}

// ---------------------------------------------------------------------------
extern "C" void kernel_launch(void* const* d_in, const int* in_sizes, int n_in,
                              void* d_out, int out_size) {
    const float* obs = (const float*)d_in[0];
    const float* c1w = (const float*)d_in[1];
    const float* c1b = (const float*)d_in[2];
    const float* c2w = (const float*)d_in[3];
    const float* c2b = (const float*)d_in[4];
    const float* ipw = (const float*)d_in[5];
    const float* ipb = (const float*)d_in[6];
    const float* opw = (const float*)d_in[7];
    const float* opb = (const float*)d_in[8];
    const float* l1w = (const float*)d_in[9];
    const float* l1b = (const float*)d_in[10];
    const float* l2w = (const float*)d_in[11];
    const float* l2b = (const float*)d_in[12];
    const float* g1  = (const float*)d_in[13];
    const float* b1  = (const float*)d_in[14];
    const float* g2  = (const float*)d_in[15];
    const float* b2  = (const float*)d_in[16];
    float* out = (float*)d_out;

    front<<<148, 256>>>(obs, c1w, c1b, c2w, c2b, ipw, ipb);
    attn_tok<<<HW, 512>>>(opw, opb, g1, b1);
    ffn0<<<dim3((S + 255) / 256, 1, NFSEG), 128>>>(l1w, l1b, l2w);
    ffnred_qkv<<<(S + 31) / 32, 256>>>(ipw + 102 * Dm, ipb + 102, l2b, g2, b2);
    agent_tail<<<148, 256>>>(opw + Dm * Dm, opb + Dm, g1 + Dm, b1 + Dm,
                             l1w + FFd * Dm, l1b + FFd, l2w + Dm * FFd, l2b + Dm,
                             g2 + Dm, b2 + Dm, out);
}